// round 3
// baseline (speedup 1.0000x reference)
#include <cuda_runtime.h>

namespace {
constexpr int THREADS = 256;
constexpr int S    = 64;          // samples per CTA
constexpr int T    = 10;
constexpr int DIN  = 16;
constexpr int H    = 64;
constexpr int G    = 4 * H;       // 256 gate columns
constexpr int DMLP = 30;
constexpr int DOUT = 4;
constexpr int BATCH = 65536;
constexpr int NCTA  = BATCH / S;  // 1024

// shared memory layout (float offsets)
constexpr int OFF_UP  = 0;                      // 64*256 (U1 phase1 / U2 phase2)
constexpr int OFF_W1P = OFF_UP  + H * G;        // 16*256
constexpr int OFF_W2P = OFF_W1P + DIN * G;      // 30*256
constexpr int OFF_WDS = OFF_W2P + DMLP * G;     // 64*32 (Wd padded 30->32)
constexpr int OFF_WFS = OFF_WDS + H * 32;       // 64*4
constexpr int OFF_B1P = OFF_WFS + H * DOUT;     // 256
constexpr int OFF_B2P = OFF_B1P + G;            // 256
constexpr int OFF_BDS = OFF_B2P + G;            // 32
constexpr int OFF_BFS = OFF_BDS + 32;           // 4
constexpr int OFF_HS  = OFF_BFS + 4;            // 64*64 h-state [unit][sample]
constexpr int OFF_XSH = OFF_HS  + H * S;        // 2 x 16 x 64 (double-buffered x[t])
constexpr int OFF_DSH = OFF_XSH + 2 * DIN * S;  // 300 x 64
constexpr int SMEM_FLOATS = OFF_DSH + T * DMLP * S;   // 56356
constexpr int SMEM_BYTES  = SMEM_FLOATS * 4;          // 225424 B
static_assert(OFF_HS % 4 == 0 && OFF_XSH % 4 == 0 && OFF_DSH % 4 == 0, "float4 alignment");
} // namespace

using u64 = unsigned long long;

// packed f32x2 helpers (Blackwell fma pipe does 2 fp32 FMAs per issue)
#define PACK2(d, lo, hi)  asm("mov.b64 %0, {%1, %2};" : "=l"(d) : "f"(lo), "f"(hi))
#define UNPACK2(lo, hi, s) asm("mov.b64 {%0, %1}, %2;" : "=f"(lo), "=f"(hi) : "l"(s))
#define FMA2(d, a, b, c)  asm("fma.rn.f32x2 %0, %1, %2, %3;" : "=l"(d) : "l"(a), "l"(b), "l"(c))

// accurate activations: EX2 + RCP based, rel err ~1e-7
__device__ __forceinline__ float sigm(float x) {
    return __fdividef(1.0f, 1.0f + __expf(-x));
}
__device__ __forceinline__ float tanh_acc(float x) {
    return __fdividef(2.0f, 1.0f + __expf(-2.0f * x)) - 1.0f;
}

// gate-interleaved column permutation:
// shared column p -> original gate column ((p&7)>>1)*64 + (p>>3)*2 + (p&1)
__device__ __forceinline__ int pcol(int p) {
    const int ug = p >> 3, r = p & 7;
    return ((r >> 1) << 6) + (ug << 1) + (r & 1);
}

// acc[s][r2] += (a[k][sg8+s] dup2) * (w[k][ug8+2r2], w[k][ug8+2r2+1])
// a rows have stride 64 floats; w rows stride 256.
__device__ __forceinline__ void gemm2(const float* __restrict__ a,
                                      const float* __restrict__ w,
                                      const int K, const int sg8, const int ug8,
                                      u64 acc[8][4]) {
#pragma unroll 2
    for (int k = 0; k < K; ++k) {
        const float4 h0 = *reinterpret_cast<const float4*>(a + k * 64 + sg8);
        const float4 h1 = *reinterpret_cast<const float4*>(a + k * 64 + sg8 + 4);
        const float4 w0 = *reinterpret_cast<const float4*>(w + k * G + ug8);
        const float4 w1 = *reinterpret_cast<const float4*>(w + k * G + ug8 + 4);
        u64 wp[4];
        PACK2(wp[0], w0.x, w0.y); PACK2(wp[1], w0.z, w0.w);
        PACK2(wp[2], w1.x, w1.y); PACK2(wp[3], w1.z, w1.w);
        const float hv[8] = {h0.x, h0.y, h0.z, h0.w, h1.x, h1.y, h1.z, h1.w};
        u64 hd[8];
#pragma unroll
        for (int s = 0; s < 8; ++s) PACK2(hd[s], hv[s], hv[s]);
#pragma unroll
        for (int s = 0; s < 8; ++s)
#pragma unroll
            for (int r = 0; r < 4; ++r)
                FMA2(acc[s][r], hd[s], wp[r], acc[s][r]);
    }
}

__global__ void __launch_bounds__(THREADS, 1)
rnn_kernel(const float* __restrict__ x,
           const float* __restrict__ W1, const float* __restrict__ U1, const float* __restrict__ b1,
           const float* __restrict__ Wd, const float* __restrict__ bd,
           const float* __restrict__ W2, const float* __restrict__ U2, const float* __restrict__ b2,
           const float* __restrict__ Wf, const float* __restrict__ bf,
           float* __restrict__ out)
{
    extern __shared__ float sm[];
    float* Up  = sm + OFF_UP;
    float* W1p = sm + OFF_W1P;
    float* W2p = sm + OFF_W2P;
    float* Wds = sm + OFF_WDS;
    float* Wfs = sm + OFF_WFS;
    float* b1p = sm + OFF_B1P;
    float* b2p = sm + OFF_B2P;
    float* bds = sm + OFF_BDS;
    float* bfs = sm + OFF_BFS;
    float* hs  = sm + OFF_HS;
    float* xsh = sm + OFF_XSH;
    float* dsh = sm + OFF_DSH;

    const int tid = threadIdx.x;
    const int sg8 = (tid & 7) << 3;   // 8 sample-groups * 8 samples = 64
    const int ug8 = (tid >> 3) << 3;  // 32 gate-groups * 8 perm cols = 256

    // ---- stage weights (permuted) into shared ----
    for (int idx = tid; idx < H * G; idx += THREADS) {
        const int k = idx >> 8, p = idx & 255;
        Up[idx] = U1[(k << 8) + pcol(p)];
    }
    for (int idx = tid; idx < DIN * G; idx += THREADS) {
        const int k = idx >> 8, p = idx & 255;
        W1p[idx] = W1[(k << 8) + pcol(p)];
    }
    for (int idx = tid; idx < DMLP * G; idx += THREADS) {
        const int k = idx >> 8, p = idx & 255;
        W2p[idx] = W2[(k << 8) + pcol(p)];
    }
    for (int idx = tid; idx < G; idx += THREADS) {
        const int c0 = pcol(idx);
        b1p[idx] = b1[c0];
        b2p[idx] = b2[c0];
    }
    for (int idx = tid; idx < H * 32; idx += THREADS) {
        const int k = idx >> 5, j = idx & 31;
        Wds[idx] = (j < DMLP) ? Wd[k * DMLP + j] : 0.0f;
    }
    if (tid < H * DOUT) Wfs[tid] = Wf[tid];
    if (tid < 32)  bds[tid] = (tid < DMLP) ? bd[tid] : 0.0f;
    if (tid < DOUT) bfs[tid] = bf[tid];

    // ---- stage x[t=0] into buffer 0 ----
    const float* xg = x + (size_t)blockIdx.x * (S * T * DIN);
    const int xs  = tid & 63;        // sample
    const int xkg = (tid >> 6) << 2; // k group of 4
    {
        const float4 v = *reinterpret_cast<const float4*>(xg + xs * (T * DIN) + xkg);
        xsh[(xkg + 0) * 64 + xs] = v.x;
        xsh[(xkg + 1) * 64 + xs] = v.y;
        xsh[(xkg + 2) * 64 + xs] = v.z;
        xsh[(xkg + 3) * 64 + xs] = v.w;
    }
    __syncthreads();

    u64 bg2[4];
#pragma unroll
    for (int r = 0; r < 4; ++r) PACK2(bg2[r], b1p[ug8 + 2 * r], b1p[ug8 + 2 * r + 1]);

    u64 dbias2;
    const int dj  = tid >> 3;         // dense output col (0..31, >=30 idle)
    const int ds8 = (tid & 7) << 3;   // dense sample group
    {
        const float bj = (dj < DMLP) ? bds[dj] : 0.0f;
        PACK2(dbias2, bj, bj);
    }

    float cst[8][2];
#pragma unroll
    for (int s = 0; s < 8; ++s) { cst[s][0] = 0.0f; cst[s][1] = 0.0f; }

    const int u0 = (tid >> 3) << 1;   // first of this thread's 2 hidden units

    // ================= phase 1: LSTM1 (tanh) + Dense =================
    for (int t = 0; t < T; ++t) {
        // prefetch x[t+1] to registers (hidden behind the GEMMs)
        float4 xr = make_float4(0.f, 0.f, 0.f, 0.f);
        if (t + 1 < T)
            xr = *reinterpret_cast<const float4*>(xg + xs * (T * DIN) + (t + 1) * DIN + xkg);

        u64 acc[8][4];
#pragma unroll
        for (int s = 0; s < 8; ++s)
#pragma unroll
            for (int r = 0; r < 4; ++r) acc[s][r] = bg2[r];

        gemm2(xsh + (t & 1) * (DIN * S), W1p, DIN, sg8, ug8, acc);
        if (t > 0) gemm2(hs, Up, H, sg8, ug8, acc);   // h0 = 0: skip

        float hh0[8], hh1[8];
#pragma unroll
        for (int s = 0; s < 8; ++s) {
            float val[8];
            UNPACK2(val[0], val[1], acc[s][0]);
            UNPACK2(val[2], val[3], acc[s][1]);
            UNPACK2(val[4], val[5], acc[s][2]);
            UNPACK2(val[6], val[7], acc[s][3]);
#pragma unroll
            for (int e = 0; e < 2; ++e) {
                const float ig = sigm(val[0 + e]);
                const float fg = sigm(val[2 + e]);
                const float gg = tanh_acc(val[4 + e]);
                const float og = sigm(val[6 + e]);
                const float cc = fmaf(fg, cst[s][e], ig * gg);
                cst[s][e] = cc;
                const float hv = og * tanh_acc(cc);
                if (e == 0) hh0[s] = hv; else hh1[s] = hv;
            }
        }
        __syncthreads();   // all readers of old hs / xsh[(t+1)&1] done
        *reinterpret_cast<float4*>(hs + u0 * 64 + sg8)           = make_float4(hh0[0], hh0[1], hh0[2], hh0[3]);
        *reinterpret_cast<float4*>(hs + u0 * 64 + sg8 + 4)       = make_float4(hh0[4], hh0[5], hh0[6], hh0[7]);
        *reinterpret_cast<float4*>(hs + (u0 + 1) * 64 + sg8)     = make_float4(hh1[0], hh1[1], hh1[2], hh1[3]);
        *reinterpret_cast<float4*>(hs + (u0 + 1) * 64 + sg8 + 4) = make_float4(hh1[4], hh1[5], hh1[6], hh1[7]);
        if (t + 1 < T) {
            float* xb = xsh + ((t + 1) & 1) * (DIN * S);
            xb[(xkg + 0) * 64 + xs] = xr.x;
            xb[(xkg + 1) * 64 + xs] = xr.y;
            xb[(xkg + 2) * 64 + xs] = xr.z;
            xb[(xkg + 3) * 64 + xs] = xr.w;
        }
        __syncthreads();   // new hs + x visible

        // Dense: d[t] = h1[t] @ Wd + bd  -> dsh (f32x2 over sample pairs)
        if (dj < DMLP) {
            u64 dacc[4];
#pragma unroll
            for (int r = 0; r < 4; ++r) dacc[r] = dbias2;
#pragma unroll 4
            for (int k = 0; k < H; ++k) {
                const float4 h0 = *reinterpret_cast<const float4*>(hs + k * 64 + ds8);
                const float4 h1 = *reinterpret_cast<const float4*>(hs + k * 64 + ds8 + 4);
                const float wv = Wds[k * 32 + dj];
                u64 wd; PACK2(wd, wv, wv);
                u64 hp[4];
                PACK2(hp[0], h0.x, h0.y); PACK2(hp[1], h0.z, h0.w);
                PACK2(hp[2], h1.x, h1.y); PACK2(hp[3], h1.z, h1.w);
#pragma unroll
                for (int r = 0; r < 4; ++r) FMA2(dacc[r], hp[r], wd, dacc[r]);
            }
            float dv[8];
            UNPACK2(dv[0], dv[1], dacc[0]);
            UNPACK2(dv[2], dv[3], dacc[1]);
            UNPACK2(dv[4], dv[5], dacc[2]);
            UNPACK2(dv[6], dv[7], dacc[3]);
            float* drow = dsh + (t * DMLP + dj) * 64 + ds8;
            *reinterpret_cast<float4*>(drow)     = make_float4(dv[0], dv[1], dv[2], dv[3]);
            *reinterpret_cast<float4*>(drow + 4) = make_float4(dv[4], dv[5], dv[6], dv[7]);
        }
    }

    // ================= phase boundary: swap U1 -> U2 =================
    __syncthreads();
    for (int idx = tid; idx < H * G; idx += THREADS) {
        const int k = idx >> 8, p = idx & 255;
        Up[idx] = U2[(k << 8) + pcol(p)];
    }
#pragma unroll
    for (int r = 0; r < 4; ++r) PACK2(bg2[r], b2p[ug8 + 2 * r], b2p[ug8 + 2 * r + 1]);
#pragma unroll
    for (int s = 0; s < 8; ++s) { cst[s][0] = 0.0f; cst[s][1] = 0.0f; }
    __syncthreads();

    // ================= phase 2: LSTM2 (relu) =================
    for (int t = 0; t < T; ++t) {
        u64 acc[8][4];
#pragma unroll
        for (int s = 0; s < 8; ++s)
#pragma unroll
            for (int r = 0; r < 4; ++r) acc[s][r] = bg2[r];

        gemm2(dsh + t * (DMLP * S), W2p, DMLP, sg8, ug8, acc);
        if (t > 0) gemm2(hs, Up, H, sg8, ug8, acc);

        float hh0[8], hh1[8];
#pragma unroll
        for (int s = 0; s < 8; ++s) {
            float val[8];
            UNPACK2(val[0], val[1], acc[s][0]);
            UNPACK2(val[2], val[3], acc[s][1]);
            UNPACK2(val[4], val[5], acc[s][2]);
            UNPACK2(val[6], val[7], acc[s][3]);
#pragma unroll
            for (int e = 0; e < 2; ++e) {
                const float ig = sigm(val[0 + e]);
                const float fg = sigm(val[2 + e]);
                const float gg = fmaxf(val[4 + e], 0.0f);   // relu activation
                const float og = sigm(val[6 + e]);
                const float cc = fmaf(fg, cst[s][e], ig * gg);
                cst[s][e] = cc;
                const float hv = og * fmaxf(cc, 0.0f);
                if (e == 0) hh0[s] = hv; else hh1[s] = hv;
            }
        }
        __syncthreads();
        *reinterpret_cast<float4*>(hs + u0 * 64 + sg8)           = make_float4(hh0[0], hh0[1], hh0[2], hh0[3]);
        *reinterpret_cast<float4*>(hs + u0 * 64 + sg8 + 4)       = make_float4(hh0[4], hh0[5], hh0[6], hh0[7]);
        *reinterpret_cast<float4*>(hs + (u0 + 1) * 64 + sg8)     = make_float4(hh1[0], hh1[1], hh1[2], hh1[3]);
        *reinterpret_cast<float4*>(hs + (u0 + 1) * 64 + sg8 + 4) = make_float4(hh1[4], hh1[5], hh1[6], hh1[7]);
        __syncthreads();
    }

    // ================= head: out = h2_last @ Wf + bf =================
    float* outg = out + (size_t)blockIdx.x * (S * DOUT);
    {
        const int s = tid >> 2, j = tid & 3;   // 64 samples x 4 outputs = 256
        float a = bfs[j];
#pragma unroll 8
        for (int k = 0; k < H; ++k)
            a = fmaf(hs[k * 64 + s], Wfs[k * DOUT + j], a);
        outg[s * DOUT + j] = a;
    }
}

extern "C" void kernel_launch(void* const* d_in, const int* in_sizes, int n_in,
                              void* d_out, int out_size) {
    (void)in_sizes; (void)n_in; (void)out_size;
    const float* x  = (const float*)d_in[0];
    const float* W1 = (const float*)d_in[1];
    const float* U1 = (const float*)d_in[2];
    const float* b1 = (const float*)d_in[3];
    const float* Wd = (const float*)d_in[4];
    const float* bd = (const float*)d_in[5];
    const float* W2 = (const float*)d_in[6];
    const float* U2 = (const float*)d_in[7];
    const float* b2 = (const float*)d_in[8];
    const float* Wf = (const float*)d_in[9];
    const float* bf = (const float*)d_in[10];
    float* out = (float*)d_out;

    cudaFuncSetAttribute(rnn_kernel, cudaFuncAttributeMaxDynamicSharedMemorySize, SMEM_BYTES);
    rnn_kernel<<<NCTA, THREADS, SMEM_BYTES>>>(x, W1, U1, b1, Wd, bd, W2, U2, b2, Wf, bf, out);
}

// round 4
// speedup vs baseline: 1.0006x; 1.0006x over previous
#include <cuda_runtime.h>

namespace {
constexpr int THREADS = 256;
constexpr int S    = 64;          // samples per CTA
constexpr int T    = 10;
constexpr int DIN  = 16;
constexpr int H    = 64;
constexpr int G    = 4 * H;       // 256 gate columns
constexpr int DMLP = 30;
constexpr int DOUT = 4;
constexpr int BATCH = 65536;
constexpr int NCTA  = BATCH / S;  // 1024

// shared memory layout (float offsets)
constexpr int OFF_UP  = 0;                      // 64*256 (U1 phase1 / U2 phase2)
constexpr int OFF_W1P = OFF_UP  + H * G;        // 16*256
constexpr int OFF_W2P = OFF_W1P + DIN * G;      // 30*256
constexpr int OFF_WDS = OFF_W2P + DMLP * G;     // 64*32 (Wd padded 30->32)
constexpr int OFF_WFS = OFF_WDS + H * 32;       // 64*4
constexpr int OFF_B1P = OFF_WFS + H * DOUT;     // 256
constexpr int OFF_B2P = OFF_B1P + G;            // 256
constexpr int OFF_BDS = OFF_B2P + G;            // 32
constexpr int OFF_BFS = OFF_BDS + 32;           // 4
constexpr int OFF_HS  = OFF_BFS + 4;            // 64*64 h-state [unit][sample]
constexpr int OFF_XSH = OFF_HS  + H * S;        // 2 x 16 x 64 (double-buffered x[t])
constexpr int OFF_DSH = OFF_XSH + 2 * DIN * S;  // 300 x 64
constexpr int SMEM_FLOATS = OFF_DSH + T * DMLP * S;   // 56356
constexpr int SMEM_BYTES  = SMEM_FLOATS * 4;          // 225424 B
static_assert(OFF_HS % 4 == 0 && OFF_XSH % 4 == 0 && OFF_DSH % 4 == 0, "float4 alignment");
} // namespace

using u64 = unsigned long long;

// packed f32x2 helpers (Blackwell fma pipe does 2 fp32 FMAs per issue)
#define PACK2(d, lo, hi)  asm("mov.b64 %0, {%1, %2};" : "=l"(d) : "f"(lo), "f"(hi))
#define UNPACK2(lo, hi, s) asm("mov.b64 {%0, %1}, %2;" : "=f"(lo), "=f"(hi) : "l"(s))
#define FMA2(d, a, b, c)  asm("fma.rn.f32x2 %0, %1, %2, %3;" : "=l"(d) : "l"(a), "l"(b), "l"(c))

// accurate activations: EX2 + RCP based, rel err ~1e-7
__device__ __forceinline__ float sigm(float x) {
    return __fdividef(1.0f, 1.0f + __expf(-x));
}
__device__ __forceinline__ float tanh_acc(float x) {
    return __fdividef(2.0f, 1.0f + __expf(-2.0f * x)) - 1.0f;
}

// gate-interleaved column permutation:
// shared column p -> original gate column ((p&7)>>1)*64 + (p>>3)*2 + (p&1)
__device__ __forceinline__ int pcol(int p) {
    const int ug = p >> 3, r = p & 7;
    return ((r >> 1) << 6) + (ug << 1) + (r & 1);
}

// acc[s][r2] += (a[k][sg8+s] dup2) * (w[k][ug8+2r2], w[k][ug8+2r2+1])
// a rows have stride 64 floats; w rows stride 256.
__device__ __forceinline__ void gemm2(const float* __restrict__ a,
                                      const float* __restrict__ w,
                                      const int K, const int sg8, const int ug8,
                                      u64 acc[8][4]) {
#pragma unroll 2
    for (int k = 0; k < K; ++k) {
        const float4 h0 = *reinterpret_cast<const float4*>(a + k * 64 + sg8);
        const float4 h1 = *reinterpret_cast<const float4*>(a + k * 64 + sg8 + 4);
        const float4 w0 = *reinterpret_cast<const float4*>(w + k * G + ug8);
        const float4 w1 = *reinterpret_cast<const float4*>(w + k * G + ug8 + 4);
        u64 wp[4];
        PACK2(wp[0], w0.x, w0.y); PACK2(wp[1], w0.z, w0.w);
        PACK2(wp[2], w1.x, w1.y); PACK2(wp[3], w1.z, w1.w);
        const float hv[8] = {h0.x, h0.y, h0.z, h0.w, h1.x, h1.y, h1.z, h1.w};
        u64 hd[8];
#pragma unroll
        for (int s = 0; s < 8; ++s) PACK2(hd[s], hv[s], hv[s]);
#pragma unroll
        for (int s = 0; s < 8; ++s)
#pragma unroll
            for (int r = 0; r < 4; ++r)
                FMA2(acc[s][r], hd[s], wp[r], acc[s][r]);
    }
}

__global__ void __launch_bounds__(THREADS, 1)
rnn_kernel(const float* __restrict__ x,
           const float* __restrict__ W1, const float* __restrict__ U1, const float* __restrict__ b1,
           const float* __restrict__ Wd, const float* __restrict__ bd,
           const float* __restrict__ W2, const float* __restrict__ U2, const float* __restrict__ b2,
           const float* __restrict__ Wf, const float* __restrict__ bf,
           float* __restrict__ out)
{
    extern __shared__ float sm[];
    float* Up  = sm + OFF_UP;
    float* W1p = sm + OFF_W1P;
    float* W2p = sm + OFF_W2P;
    float* Wds = sm + OFF_WDS;
    float* Wfs = sm + OFF_WFS;
    float* b1p = sm + OFF_B1P;
    float* b2p = sm + OFF_B2P;
    float* bds = sm + OFF_BDS;
    float* bfs = sm + OFF_BFS;
    float* hs  = sm + OFF_HS;
    float* xsh = sm + OFF_XSH;
    float* dsh = sm + OFF_DSH;

    const int tid = threadIdx.x;
    const int sg8 = (tid & 7) << 3;   // 8 sample-groups * 8 samples = 64
    const int ug8 = (tid >> 3) << 3;  // 32 gate-groups * 8 perm cols = 256

    // ---- stage weights (permuted) into shared ----
    for (int idx = tid; idx < H * G; idx += THREADS) {
        const int k = idx >> 8, p = idx & 255;
        Up[idx] = U1[(k << 8) + pcol(p)];
    }
    for (int idx = tid; idx < DIN * G; idx += THREADS) {
        const int k = idx >> 8, p = idx & 255;
        W1p[idx] = W1[(k << 8) + pcol(p)];
    }
    for (int idx = tid; idx < DMLP * G; idx += THREADS) {
        const int k = idx >> 8, p = idx & 255;
        W2p[idx] = W2[(k << 8) + pcol(p)];
    }
    for (int idx = tid; idx < G; idx += THREADS) {
        const int c0 = pcol(idx);
        b1p[idx] = b1[c0];
        b2p[idx] = b2[c0];
    }
    for (int idx = tid; idx < H * 32; idx += THREADS) {
        const int k = idx >> 5, j = idx & 31;
        Wds[idx] = (j < DMLP) ? Wd[k * DMLP + j] : 0.0f;
    }
    if (tid < H * DOUT) Wfs[tid] = Wf[tid];
    if (tid < 32)  bds[tid] = (tid < DMLP) ? bd[tid] : 0.0f;
    if (tid < DOUT) bfs[tid] = bf[tid];

    // ---- stage x[t=0] into buffer 0 ----
    const float* xg = x + (size_t)blockIdx.x * (S * T * DIN);
    const int xs  = tid & 63;        // sample
    const int xkg = (tid >> 6) << 2; // k group of 4
    {
        const float4 v = *reinterpret_cast<const float4*>(xg + xs * (T * DIN) + xkg);
        xsh[(xkg + 0) * 64 + xs] = v.x;
        xsh[(xkg + 1) * 64 + xs] = v.y;
        xsh[(xkg + 2) * 64 + xs] = v.z;
        xsh[(xkg + 3) * 64 + xs] = v.w;
    }
    __syncthreads();

    u64 bg2[4];
#pragma unroll
    for (int r = 0; r < 4; ++r) PACK2(bg2[r], b1p[ug8 + 2 * r], b1p[ug8 + 2 * r + 1]);

    u64 dbias2;
    const int dj  = tid >> 3;         // dense output col (0..31, >=30 idle)
    const int ds8 = (tid & 7) << 3;   // dense sample group
    {
        const float bj = (dj < DMLP) ? bds[dj] : 0.0f;
        PACK2(dbias2, bj, bj);
    }

    float cst[8][2];
#pragma unroll
    for (int s = 0; s < 8; ++s) { cst[s][0] = 0.0f; cst[s][1] = 0.0f; }

    const int u0 = (tid >> 3) << 1;   // first of this thread's 2 hidden units

    // ================= phase 1: LSTM1 (tanh) + Dense =================
    for (int t = 0; t < T; ++t) {
        // prefetch x[t+1] to registers (hidden behind the GEMMs)
        float4 xr = make_float4(0.f, 0.f, 0.f, 0.f);
        if (t + 1 < T)
            xr = *reinterpret_cast<const float4*>(xg + xs * (T * DIN) + (t + 1) * DIN + xkg);

        u64 acc[8][4];
#pragma unroll
        for (int s = 0; s < 8; ++s)
#pragma unroll
            for (int r = 0; r < 4; ++r) acc[s][r] = bg2[r];

        gemm2(xsh + (t & 1) * (DIN * S), W1p, DIN, sg8, ug8, acc);
        if (t > 0) gemm2(hs, Up, H, sg8, ug8, acc);   // h0 = 0: skip

        float hh0[8], hh1[8];
#pragma unroll
        for (int s = 0; s < 8; ++s) {
            float val[8];
            UNPACK2(val[0], val[1], acc[s][0]);
            UNPACK2(val[2], val[3], acc[s][1]);
            UNPACK2(val[4], val[5], acc[s][2]);
            UNPACK2(val[6], val[7], acc[s][3]);
#pragma unroll
            for (int e = 0; e < 2; ++e) {
                const float ig = sigm(val[0 + e]);
                const float fg = sigm(val[2 + e]);
                const float gg = tanh_acc(val[4 + e]);
                const float og = sigm(val[6 + e]);
                const float cc = fmaf(fg, cst[s][e], ig * gg);
                cst[s][e] = cc;
                const float hv = og * tanh_acc(cc);
                if (e == 0) hh0[s] = hv; else hh1[s] = hv;
            }
        }
        __syncthreads();   // all readers of old hs / xsh[(t+1)&1] done
        *reinterpret_cast<float4*>(hs + u0 * 64 + sg8)           = make_float4(hh0[0], hh0[1], hh0[2], hh0[3]);
        *reinterpret_cast<float4*>(hs + u0 * 64 + sg8 + 4)       = make_float4(hh0[4], hh0[5], hh0[6], hh0[7]);
        *reinterpret_cast<float4*>(hs + (u0 + 1) * 64 + sg8)     = make_float4(hh1[0], hh1[1], hh1[2], hh1[3]);
        *reinterpret_cast<float4*>(hs + (u0 + 1) * 64 + sg8 + 4) = make_float4(hh1[4], hh1[5], hh1[6], hh1[7]);
        if (t + 1 < T) {
            float* xb = xsh + ((t + 1) & 1) * (DIN * S);
            xb[(xkg + 0) * 64 + xs] = xr.x;
            xb[(xkg + 1) * 64 + xs] = xr.y;
            xb[(xkg + 2) * 64 + xs] = xr.z;
            xb[(xkg + 3) * 64 + xs] = xr.w;
        }
        __syncthreads();   // new hs + x visible

        // Dense: d[t] = h1[t] @ Wd + bd  -> dsh (f32x2 over sample pairs)
        if (dj < DMLP) {
            u64 dacc[4];
#pragma unroll
            for (int r = 0; r < 4; ++r) dacc[r] = dbias2;
#pragma unroll 4
            for (int k = 0; k < H; ++k) {
                const float4 h0 = *reinterpret_cast<const float4*>(hs + k * 64 + ds8);
                const float4 h1 = *reinterpret_cast<const float4*>(hs + k * 64 + ds8 + 4);
                const float wv = Wds[k * 32 + dj];
                u64 wd; PACK2(wd, wv, wv);
                u64 hp[4];
                PACK2(hp[0], h0.x, h0.y); PACK2(hp[1], h0.z, h0.w);
                PACK2(hp[2], h1.x, h1.y); PACK2(hp[3], h1.z, h1.w);
#pragma unroll
                for (int r = 0; r < 4; ++r) FMA2(dacc[r], hp[r], wd, dacc[r]);
            }
            float dv[8];
            UNPACK2(dv[0], dv[1], dacc[0]);
            UNPACK2(dv[2], dv[3], dacc[1]);
            UNPACK2(dv[4], dv[5], dacc[2]);
            UNPACK2(dv[6], dv[7], dacc[3]);
            float* drow = dsh + (t * DMLP + dj) * 64 + ds8;
            *reinterpret_cast<float4*>(drow)     = make_float4(dv[0], dv[1], dv[2], dv[3]);
            *reinterpret_cast<float4*>(drow + 4) = make_float4(dv[4], dv[5], dv[6], dv[7]);
        }
    }

    // ================= phase boundary: swap U1 -> U2 =================
    __syncthreads();
    for (int idx = tid; idx < H * G; idx += THREADS) {
        const int k = idx >> 8, p = idx & 255;
        Up[idx] = U2[(k << 8) + pcol(p)];
    }
#pragma unroll
    for (int r = 0; r < 4; ++r) PACK2(bg2[r], b2p[ug8 + 2 * r], b2p[ug8 + 2 * r + 1]);
#pragma unroll
    for (int s = 0; s < 8; ++s) { cst[s][0] = 0.0f; cst[s][1] = 0.0f; }
    __syncthreads();

    // ================= phase 2: LSTM2 (relu) =================
    for (int t = 0; t < T; ++t) {
        u64 acc[8][4];
#pragma unroll
        for (int s = 0; s < 8; ++s)
#pragma unroll
            for (int r = 0; r < 4; ++r) acc[s][r] = bg2[r];

        gemm2(dsh + t * (DMLP * S), W2p, DMLP, sg8, ug8, acc);
        if (t > 0) gemm2(hs, Up, H, sg8, ug8, acc);

        float hh0[8], hh1[8];
#pragma unroll
        for (int s = 0; s < 8; ++s) {
            float val[8];
            UNPACK2(val[0], val[1], acc[s][0]);
            UNPACK2(val[2], val[3], acc[s][1]);
            UNPACK2(val[4], val[5], acc[s][2]);
            UNPACK2(val[6], val[7], acc[s][3]);
#pragma unroll
            for (int e = 0; e < 2; ++e) {
                const float ig = sigm(val[0 + e]);
                const float fg = sigm(val[2 + e]);
                const float gg = fmaxf(val[4 + e], 0.0f);   // relu activation
                const float og = sigm(val[6 + e]);
                const float cc = fmaf(fg, cst[s][e], ig * gg);
                cst[s][e] = cc;
                const float hv = og * fmaxf(cc, 0.0f);
                if (e == 0) hh0[s] = hv; else hh1[s] = hv;
            }
        }
        __syncthreads();
        *reinterpret_cast<float4*>(hs + u0 * 64 + sg8)           = make_float4(hh0[0], hh0[1], hh0[2], hh0[3]);
        *reinterpret_cast<float4*>(hs + u0 * 64 + sg8 + 4)       = make_float4(hh0[4], hh0[5], hh0[6], hh0[7]);
        *reinterpret_cast<float4*>(hs + (u0 + 1) * 64 + sg8)     = make_float4(hh1[0], hh1[1], hh1[2], hh1[3]);
        *reinterpret_cast<float4*>(hs + (u0 + 1) * 64 + sg8 + 4) = make_float4(hh1[4], hh1[5], hh1[6], hh1[7]);
        __syncthreads();
    }

    // ================= head: out = h2_last @ Wf + bf =================
    float* outg = out + (size_t)blockIdx.x * (S * DOUT);
    {
        const int s = tid >> 2, j = tid & 3;   // 64 samples x 4 outputs = 256
        float a = bfs[j];
#pragma unroll 8
        for (int k = 0; k < H; ++k)
            a = fmaf(hs[k * 64 + s], Wfs[k * DOUT + j], a);
        outg[s * DOUT + j] = a;
    }
}

extern "C" void kernel_launch(void* const* d_in, const int* in_sizes, int n_in,
                              void* d_out, int out_size) {
    (void)in_sizes; (void)n_in; (void)out_size;
    const float* x  = (const float*)d_in[0];
    const float* W1 = (const float*)d_in[1];
    const float* U1 = (const float*)d_in[2];
    const float* b1 = (const float*)d_in[3];
    const float* Wd = (const float*)d_in[4];
    const float* bd = (const float*)d_in[5];
    const float* W2 = (const float*)d_in[6];
    const float* U2 = (const float*)d_in[7];
    const float* b2 = (const float*)d_in[8];
    const float* Wf = (const float*)d_in[9];
    const float* bf = (const float*)d_in[10];
    float* out = (float*)d_out;

    cudaFuncSetAttribute(rnn_kernel, cudaFuncAttributeMaxDynamicSharedMemorySize, SMEM_BYTES);
    rnn_kernel<<<NCTA, THREADS, SMEM_BYTES>>>(x, W1, U1, b1, Wd, bd, W2, U2, b2, Wf, bf, out);
}

// round 7
// speedup vs baseline: 1.9373x; 1.9361x over previous
#include <cuda_runtime.h>
#include <cuda_bf16.h>
#include <cstdint>

namespace {
constexpr int TT = 10;
constexpr int NTILES = 2048;      // 65536 samples / 32 per tile
constexpr int GRID = 148;
// smem byte offsets. Big B-tiles: [256 n][64 k] bf16, 128B rows, swizzled.
constexpr int U1HI = 0, U1LO = 32768, U2HI = 65536, U2LO = 98304;
constexpr int FHI = 131072, FLO = 163840;
constexpr int W1T = 196608;       // [256 n][32 k]: k0-15=W1hi, k16-31=W1lo (64B rows)
constexpr int HT1HI = 212992, HT1LO = 217088, HT2HI = 221184, HT2LO = 225280; // [32 s][64 u]
constexpr int BIAS1 = 229376, BIAS2 = 230400;
constexpr int SMEM_BYTES = 231424;
}

__device__ float g_Wf[64 * 256];
__device__ float g_b2p[256];

__device__ __forceinline__ uint32_t s2u(const void* p) {
    uint32_t a;
    asm("{.reg .u64 t; cvta.to.shared.u64 t,%1; cvt.u32.u64 %0,t;}" : "=r"(a) : "l"(p));
    return a;
}
__device__ __forceinline__ void ldsm4(uint32_t a, uint32_t* r) {
    asm volatile("ldmatrix.sync.aligned.m8n8.x4.shared.b16 {%0,%1,%2,%3},[%4];"
        : "=r"(r[0]), "=r"(r[1]), "=r"(r[2]), "=r"(r[3]) : "r"(a));
}
__device__ __forceinline__ void mma(float* d, const uint32_t* a, uint32_t b0, uint32_t b1) {
    asm volatile("mma.sync.aligned.m16n8k16.row.col.f32.bf16.bf16.f32 "
        "{%0,%1,%2,%3},{%4,%5,%6,%7},{%8,%9},{%0,%1,%2,%3};"
        : "+f"(d[0]), "+f"(d[1]), "+f"(d[2]), "+f"(d[3])
        : "r"(a[0]), "r"(a[1]), "r"(a[2]), "r"(a[3]), "r"(b0), "r"(b1));
}
__device__ __forceinline__ float sigm(float x) { return __fdividef(1.f, 1.f + __expf(-x)); }
__device__ __forceinline__ float tha(float x)  { return __fdividef(2.f, 1.f + __expf(-2.f * x)) - 1.f; }
__device__ __forceinline__ uint32_t pk(float a, float b) {
    __nv_bfloat162 t = __floats2bfloat162_rn(a, b);
    return *reinterpret_cast<uint32_t*>(&t);
}
__device__ __forceinline__ float bfr(float v) { return __bfloat162float(__float2bfloat16(v)); }
__device__ __forceinline__ int sw8(int r) { return (r + (r >> 3)) & 7; }

__global__ void prep_kernel(const float* __restrict__ Wd, const float* __restrict__ bd,
                            const float* __restrict__ W2, const float* __restrict__ b2) {
    const int n = threadIdx.x;
    float s2 = b2[n];
    for (int j = 0; j < 30; ++j) s2 += bd[j] * W2[j * 256 + n];
    g_b2p[n] = s2;
    for (int k = 0; k < 64; ++k) {
        float s = 0.f;
        for (int j = 0; j < 30; ++j) s += Wd[k * 30 + j] * W2[j * 256 + n];
        g_Wf[k * 256 + n] = s;
    }
}

__global__ void __launch_bounds__(256, 1)
rnn_mma_kernel(const float* __restrict__ x, const float* __restrict__ W1,
               const float* __restrict__ U1, const float* __restrict__ b1,
               const float* __restrict__ U2, const float* __restrict__ Wf,
               const float* __restrict__ bf, float* __restrict__ out)
{
    extern __shared__ char sm[];
    const uint32_t sb = s2u(sm);
    const int tid = threadIdx.x, wid = tid >> 5, lid = tid & 31;
    const int mt = wid & 1, nq = wid >> 1;     // m-tile, n-quarter (= unit group of 16)
    const int grp = lid >> 2, tig = lid & 3;
    float* b1s = reinterpret_cast<float*>(sm + BIAS1);
    float* b2s = reinterpret_cast<float*>(sm + BIAS2);

    // stored col p -> orig gate col: gate=(p>>4)&3, unit=(p>>6)*16+(p&15)
    auto ocol = [](int p) { return (((p >> 4) & 3) << 6) + ((p >> 6) << 4) + (p & 15); };

    // ---- stage weights once (persistent CTA) ----
    auto stage = [&](const float* src, int oh, int ol) {
        for (int idx = tid; idx < 2048; idx += 256) {
            const int p = idx >> 3, kc = idx & 7;
            const float* s0 = src + ocol(p);
            uint32_t hi[4], lo[4];
#pragma unroll
            for (int i = 0; i < 4; ++i) {
                const float a = s0[(kc * 8 + 2 * i) * 256];
                const float b = s0[(kc * 8 + 2 * i + 1) * 256];
                hi[i] = pk(a, b);
                lo[i] = pk(a - bfr(a), b - bfr(b));
            }
            const int ad = p * 128 + ((kc ^ sw8(p)) << 4);
            *reinterpret_cast<uint4*>(sm + oh + ad) = *reinterpret_cast<uint4*>(hi);
            *reinterpret_cast<uint4*>(sm + ol + ad) = *reinterpret_cast<uint4*>(lo);
        }
    };
    stage(U1, U1HI, U1LO);
    stage(U2, U2HI, U2LO);
    stage(g_Wf, FHI, FLO);
    for (int idx = tid; idx < 1024; idx += 256) {   // W1 combined tile
        const int p = idx >> 2, c = idx & 3, oc = ocol(p);
        const bool isLo = c >= 2;
        const int kb = (c & 1) * 8;
        uint32_t v[4];
#pragma unroll
        for (int i = 0; i < 4; ++i) {
            float a = W1[(kb + 2 * i) * 256 + oc];
            float b = W1[(kb + 2 * i + 1) * 256 + oc];
            if (isLo) { a -= bfr(a); b -= bfr(b); }
            v[i] = pk(a, b);
        }
        *reinterpret_cast<uint4*>(sm + W1T + p * 64 + ((c ^ (p & 3)) << 4)) =
            *reinterpret_cast<uint4*>(v);
    }
    b1s[tid] = b1[tid];
    b2s[tid] = g_b2p[tid];
    __syncthreads();

    // ldmatrix address helpers
    auto bAddr = [&](int base, int jj, int kc) -> uint32_t {
        const int n = nq * 64 + jj * 16 + (lid & 15);
        const int c = kc * 2 + (lid >> 4);
        return sb + base + n * 128 + ((c ^ sw8(n)) << 4);
    };
    auto aAddr = [&](int base, int kc) -> uint32_t {
        const int r = mt * 16 + (lid & 15);
        const int c = kc * 2 + (lid >> 4);
        return sb + base + r * 128 + ((c ^ sw8(r)) << 4);
    };
    auto wAddr = [&](int jj, int half) -> uint32_t {
        const int n = nq * 64 + jj * 16 + (lid & 15);
        const int c = half * 2 + (lid >> 4);
        return sb + W1T + n * 64 + ((c ^ (n & 3)) << 4);
    };
    // split-2 GEMM chunk: acc += Ahi*Bhi + Alo*Bhi + Ahi*Blo  (term-major for dep spacing)
    auto xmmas = [&](float (*acc)[4], const uint32_t* ah, const uint32_t* al,
                     const uint32_t* bh, const uint32_t* bl) {
#pragma unroll
        for (int jj = 0; jj < 4; ++jj) {
            mma(acc[2 * jj], ah, bh[4 * jj], bh[4 * jj + 2]);
            mma(acc[2 * jj + 1], ah, bh[4 * jj + 1], bh[4 * jj + 3]);
        }
#pragma unroll
        for (int jj = 0; jj < 4; ++jj) {
            mma(acc[2 * jj], al, bh[4 * jj], bh[4 * jj + 2]);
            mma(acc[2 * jj + 1], al, bh[4 * jj + 1], bh[4 * jj + 3]);
        }
#pragma unroll
        for (int jj = 0; jj < 4; ++jj) {
            mma(acc[2 * jj], ah, bl[4 * jj], bl[4 * jj + 2]);
            mma(acc[2 * jj + 1], ah, bl[4 * jj + 1], bl[4 * jj + 3]);
        }
    };
    auto recChunk = [&](float (*acc)[4], int aHi, int aLo, int bHi, int bLo, int kc) {
        uint32_t ah[4], al[4], bh[16], bl[16];
        ldsm4(aAddr(aHi, kc), ah);
        ldsm4(aAddr(aLo, kc), al);
#pragma unroll
        for (int jj = 0; jj < 4; ++jj) {
            ldsm4(bAddr(bHi, jj, kc), bh + 4 * jj);
            ldsm4(bAddr(bLo, jj, kc), bl + 4 * jj);
        }
        xmmas(acc, ah, al, bh, bl);
    };
    // epilogue: gates (in-register!) -> LSTM -> h hi/lo tiles; optional head partials
    auto epi = [&](float (*acc)[4], float* cst, const float* bs, int hHi, int hLo,
                   bool relu, bool head, float (*pout)[4]) {
#pragma unroll
        for (int j2 = 0; j2 < 2; ++j2)
#pragma unroll
            for (int r = 0; r < 4; ++r) {
                const int u = nq * 16 + j2 * 8 + tig * 2 + (r & 1);
                const int s = mt * 16 + grp + (r >> 1) * 8;
                const float iv = sigm(acc[j2][r] + bs[u]);
                const float fv = sigm(acc[2 + j2][r] + bs[64 + u]);
                const float zg = acc[4 + j2][r] + bs[128 + u];
                const float gv = relu ? fmaxf(zg, 0.f) : tha(zg);
                const float ov = sigm(acc[6 + j2][r] + bs[192 + u]);
                const int ci = j2 * 4 + r;
                const float cc = fmaf(fv, cst[ci], iv * gv);
                cst[ci] = cc;
                const float hv = ov * (relu ? fmaxf(cc, 0.f) : tha(cc));
                const int ad = s * 128 + (((u >> 3) ^ sw8(s)) << 4) + (u & 7) * 2;
                *reinterpret_cast<__nv_bfloat16*>(sm + hHi + ad) = __float2bfloat16(hv);
                *reinterpret_cast<__nv_bfloat16*>(sm + hLo + ad) = __float2bfloat16(hv - bfr(hv));
                if (head) {
                    const float4 w = *reinterpret_cast<const float4*>(Wf + u * 4);
                    float* po = pout[r >> 1];
                    po[0] = fmaf(hv, w.x, po[0]);
                    po[1] = fmaf(hv, w.y, po[1]);
                    po[2] = fmaf(hv, w.z, po[2]);
                    po[3] = fmaf(hv, w.w, po[3]);
                }
            }
    };

    // ---- persistent tile loop: 32 samples per tile ----
    for (int tile = blockIdx.x; tile < NTILES; tile += gridDim.x) {
        float c1[8], c2[8], pout[2][4];
#pragma unroll
        for (int i = 0; i < 8; ++i) { c1[i] = 0.f; c2[i] = 0.f; }
#pragma unroll
        for (int i = 0; i < 4; ++i) { pout[0][i] = 0.f; pout[1][i] = 0.f; }
        const float* xb = x + (size_t)(tile * 32 + mt * 16 + grp) * (TT * 16) + tig * 2;

        for (int t = 0; t < TT; ++t) {
            // x A-fragments (hi/lo) from gmem
            const float* px = xb + t * 16;
            const float2 v0 = *reinterpret_cast<const float2*>(px);
            const float2 v1 = *reinterpret_cast<const float2*>(px + 8 * TT * 16);
            const float2 v2 = *reinterpret_cast<const float2*>(px + 8);
            const float2 v3 = *reinterpret_cast<const float2*>(px + 8 * TT * 16 + 8);
            const uint32_t axh[4] = {pk(v0.x, v0.y), pk(v1.x, v1.y), pk(v2.x, v2.y), pk(v3.x, v3.y)};
            const uint32_t axl[4] = {
                pk(v0.x - bfr(v0.x), v0.y - bfr(v0.y)), pk(v1.x - bfr(v1.x), v1.y - bfr(v1.y)),
                pk(v2.x - bfr(v2.x), v2.y - bfr(v2.y)), pk(v3.x - bfr(v3.x), v3.y - bfr(v3.y))};

            // ---- z1 = x@W1 + h1@U1 ----
            float acc[8][4];
#pragma unroll
            for (int j = 0; j < 8; ++j)
#pragma unroll
                for (int r = 0; r < 4; ++r) acc[j][r] = 0.f;
            {
                uint32_t bh[16], bl[16];
#pragma unroll
                for (int jj = 0; jj < 4; ++jj) {
                    ldsm4(wAddr(jj, 0), bh + 4 * jj);
                    ldsm4(wAddr(jj, 1), bl + 4 * jj);
                }
                xmmas(acc, axh, axl, bh, bl);
            }
            if (t)
#pragma unroll
                for (int kc = 0; kc < 4; ++kc) recChunk(acc, HT1HI, HT1LO, U1HI, U1LO, kc);
            __syncthreads();
            epi(acc, c1, b1s, HT1HI, HT1LO, false, false, nullptr);
            __syncthreads();

            // ---- z2 = h1@Wfused + h2@U2 ----
            float acc2[8][4];
#pragma unroll
            for (int j = 0; j < 8; ++j)
#pragma unroll
                for (int r = 0; r < 4; ++r) acc2[j][r] = 0.f;
#pragma unroll
            for (int kc = 0; kc < 4; ++kc) recChunk(acc2, HT1HI, HT1LO, FHI, FLO, kc);
            if (t)
#pragma unroll
                for (int kc = 0; kc < 4; ++kc) recChunk(acc2, HT2HI, HT2LO, U2HI, U2LO, kc);
            __syncthreads();
            epi(acc2, c2, b2s, HT2HI, HT2LO, true, t == TT - 1, pout);
            __syncthreads();
        }

        // ---- head: reduce over tig (shfl), then over nq (smem) ----
#pragma unroll
        for (int h = 0; h < 2; ++h)
#pragma unroll
            for (int o = 0; o < 4; ++o) {
                pout[h][o] += __shfl_xor_sync(0xffffffffu, pout[h][o], 1);
                pout[h][o] += __shfl_xor_sync(0xffffffffu, pout[h][o], 2);
            }
        float* scr = reinterpret_cast<float*>(sm + BIAS1);   // clobbers bias arrays
        if (tig == 0) {
            const int s0 = mt * 16 + grp;
            *reinterpret_cast<float4*>(scr + (s0 * 4 + nq) * 4) =
                make_float4(pout[0][0], pout[0][1], pout[0][2], pout[0][3]);
            *reinterpret_cast<float4*>(scr + ((s0 + 8) * 4 + nq) * 4) =
                make_float4(pout[1][0], pout[1][1], pout[1][2], pout[1][3]);
        }
        __syncthreads();
        if (tid < 128) {
            const int s = tid >> 2, o = tid & 3;
            const float v = scr[(s * 4 + 0) * 4 + o] + scr[(s * 4 + 1) * 4 + o] +
                            scr[(s * 4 + 2) * 4 + o] + scr[(s * 4 + 3) * 4 + o] + bf[o];
            out[(size_t)tile * 128 + s * 4 + o] = v;
        }
        __syncthreads();
        b1s[tid] = b1[tid];            // restore clobbered biases
        b2s[tid] = g_b2p[tid];
        __syncthreads();
    }
}

extern "C" void kernel_launch(void* const* d_in, const int* in_sizes, int n_in,
                              void* d_out, int out_size) {
    (void)in_sizes; (void)n_in; (void)out_size;
    const float* x  = (const float*)d_in[0];
    const float* W1 = (const float*)d_in[1];
    const float* U1 = (const float*)d_in[2];
    const float* b1 = (const float*)d_in[3];
    const float* Wd = (const float*)d_in[4];
    const float* bd = (const float*)d_in[5];
    const float* W2 = (const float*)d_in[6];
    const float* U2 = (const float*)d_in[7];
    const float* b2 = (const float*)d_in[8];
    const float* Wf = (const float*)d_in[9];
    const float* bf = (const float*)d_in[10];
    float* out = (float*)d_out;

    prep_kernel<<<1, 256>>>(Wd, bd, W2, b2);
    cudaFuncSetAttribute(rnn_mma_kernel, cudaFuncAttributeMaxDynamicSharedMemorySize, SMEM_BYTES);
    rnn_mma_kernel<<<GRID, 256, SMEM_BYTES>>>(x, W1, U1, b1, U2, Wf, bf, out);
}

// round 8
// speedup vs baseline: 2.1446x; 1.1070x over previous
#include <cuda_runtime.h>
#include <cuda_bf16.h>
#include <cuda_fp16.h>
#include <cstdint>

namespace {
constexpr int TT = 10;
constexpr int NTILES = 1024;      // 65536 / 64 samples per tile
constexpr int GRID = 148;
// smem offsets. bf16 B-tiles [256 n][64 k] 128B rows swizzled; U2 fp16 single.
constexpr int U1HI = 0, U1LO = 32768, FHI = 65536, FLO = 98304;
constexpr int U2F = 131072;       // fp16 [256][64] = 32768
constexpr int W1T = 163840;       // [256 n][32 k] bf16: k0-15 hi, k16-31 lo (64B rows)
constexpr int HT1HI = 180224, HT1LO = 188416;   // h1 bf16 [64 s][64 u] = 8192 each
constexpr int HT2HI = 196608, HT2LO = 204800;   // h2 fp16 [64 s][64 u]
constexpr int BIAS1 = 212992, BIAS2 = 214016;
constexpr int SMEM_BYTES = 215040;
}

__device__ float g_Wf[64 * 256];
__device__ float g_b2p[256];

__device__ __forceinline__ uint32_t s2u(const void* p) {
    uint32_t a;
    asm("{.reg .u64 t; cvta.to.shared.u64 t,%1; cvt.u32.u64 %0,t;}" : "=r"(a) : "l"(p));
    return a;
}
__device__ __forceinline__ void ldsm4(uint32_t a, uint32_t* r) {
    asm volatile("ldmatrix.sync.aligned.m8n8.x4.shared.b16 {%0,%1,%2,%3},[%4];"
        : "=r"(r[0]), "=r"(r[1]), "=r"(r[2]), "=r"(r[3]) : "r"(a));
}
__device__ __forceinline__ void mmab(float* d, const uint32_t* a, uint32_t b0, uint32_t b1) {
    asm volatile("mma.sync.aligned.m16n8k16.row.col.f32.bf16.bf16.f32 "
        "{%0,%1,%2,%3},{%4,%5,%6,%7},{%8,%9},{%0,%1,%2,%3};"
        : "+f"(d[0]), "+f"(d[1]), "+f"(d[2]), "+f"(d[3])
        : "r"(a[0]), "r"(a[1]), "r"(a[2]), "r"(a[3]), "r"(b0), "r"(b1));
}
__device__ __forceinline__ void mmah(float* d, const uint32_t* a, uint32_t b0, uint32_t b1) {
    asm volatile("mma.sync.aligned.m16n8k16.row.col.f32.f16.f16.f32 "
        "{%0,%1,%2,%3},{%4,%5,%6,%7},{%8,%9},{%0,%1,%2,%3};"
        : "+f"(d[0]), "+f"(d[1]), "+f"(d[2]), "+f"(d[3])
        : "r"(a[0]), "r"(a[1]), "r"(a[2]), "r"(a[3]), "r"(b0), "r"(b1));
}
__device__ __forceinline__ float sigm(float x) { return __fdividef(1.f, 1.f + __expf(-x)); }
__device__ __forceinline__ float tha(float x)  { return __fdividef(2.f, 1.f + __expf(-2.f * x)) - 1.f; }
__device__ __forceinline__ uint32_t pk(float a, float b) {
    __nv_bfloat162 t = __floats2bfloat162_rn(a, b);
    return *reinterpret_cast<uint32_t*>(&t);
}
__device__ __forceinline__ uint32_t pkh(float a, float b) {
    __half2 t = __floats2half2_rn(a, b);
    return *reinterpret_cast<uint32_t*>(&t);
}
__device__ __forceinline__ float bfr(float v) { return __bfloat162float(__float2bfloat16(v)); }
__device__ __forceinline__ float hfr(float v) { return __half2float(__float2half(v)); }
__device__ __forceinline__ int sw8(int r) { return (r + (r >> 3)) & 7; }

__global__ void prep_kernel(const float* __restrict__ Wd, const float* __restrict__ bd,
                            const float* __restrict__ W2, const float* __restrict__ b2) {
    const int n = threadIdx.x;
    float s2 = b2[n];
    for (int j = 0; j < 30; ++j) s2 += bd[j] * W2[j * 256 + n];
    g_b2p[n] = s2;
    for (int k = 0; k < 64; ++k) {
        float s = 0.f;
        for (int j = 0; j < 30; ++j) s += Wd[k * 30 + j] * W2[j * 256 + n];
        g_Wf[k * 256 + n] = s;
    }
}

__global__ void __launch_bounds__(256, 1)
rnn_mma_kernel(const float* __restrict__ x, const float* __restrict__ W1,
               const float* __restrict__ U1, const float* __restrict__ b1,
               const float* __restrict__ U2, const float* __restrict__ Wf,
               const float* __restrict__ bf, float* __restrict__ out)
{
    extern __shared__ char sm[];
    const uint32_t sb = s2u(sm);
    const int tid = threadIdx.x, wid = tid >> 5, lid = tid & 31;
    const int mt = wid & 1, nq = wid >> 1;
    const int grp = lid >> 2, tig = lid & 3;
    float* b1s = reinterpret_cast<float*>(sm + BIAS1);
    float* b2s = reinterpret_cast<float*>(sm + BIAS2);

    auto ocol = [](int p) { return (((p >> 4) & 3) << 6) + ((p >> 6) << 4) + (p & 15); };

    // ---- stage weights once ----
    auto stage = [&](const float* src, int oh, int ol) {
        for (int idx = tid; idx < 2048; idx += 256) {
            const int p = idx >> 3, kc = idx & 7;
            const float* s0 = src + ocol(p);
            uint32_t hi[4], lo[4];
#pragma unroll
            for (int i = 0; i < 4; ++i) {
                const float a = s0[(kc * 8 + 2 * i) * 256];
                const float b = s0[(kc * 8 + 2 * i + 1) * 256];
                hi[i] = pk(a, b);
                lo[i] = pk(a - bfr(a), b - bfr(b));
            }
            const int ad = p * 128 + ((kc ^ sw8(p)) << 4);
            *reinterpret_cast<uint4*>(sm + oh + ad) = *reinterpret_cast<uint4*>(hi);
            *reinterpret_cast<uint4*>(sm + ol + ad) = *reinterpret_cast<uint4*>(lo);
        }
    };
    stage(U1, U1HI, U1LO);
    stage(g_Wf, FHI, FLO);
    for (int idx = tid; idx < 2048; idx += 256) {   // U2 fp16 single
        const int p = idx >> 3, kc = idx & 7;
        const float* s0 = U2 + ocol(p);
        uint32_t v[4];
#pragma unroll
        for (int i = 0; i < 4; ++i)
            v[i] = pkh(s0[(kc * 8 + 2 * i) * 256], s0[(kc * 8 + 2 * i + 1) * 256]);
        *reinterpret_cast<uint4*>(sm + U2F + p * 128 + ((kc ^ sw8(p)) << 4)) =
            *reinterpret_cast<uint4*>(v);
    }
    for (int idx = tid; idx < 1024; idx += 256) {   // W1 combined
        const int p = idx >> 2, c = idx & 3, oc = ocol(p);
        const bool isLo = c >= 2;
        const int kb = (c & 1) * 8;
        uint32_t v[4];
#pragma unroll
        for (int i = 0; i < 4; ++i) {
            float a = W1[(kb + 2 * i) * 256 + oc];
            float b = W1[(kb + 2 * i + 1) * 256 + oc];
            if (isLo) { a -= bfr(a); b -= bfr(b); }
            v[i] = pk(a, b);
        }
        *reinterpret_cast<uint4*>(sm + W1T + p * 64 + ((c ^ (p & 3)) << 4)) =
            *reinterpret_cast<uint4*>(v);
    }
    b1s[tid] = b1[tid];
    b2s[tid] = g_b2p[tid];
    __syncthreads();

    auto bAddr = [&](int base, int jj, int kc) -> uint32_t {
        const int n = nq * 64 + jj * 16 + (lid & 15);
        const int c = kc * 2 + (lid >> 4);
        return sb + base + n * 128 + ((c ^ sw8(n)) << 4);
    };
    auto aAddr = [&](int base, int mf, int kc) -> uint32_t {
        const int r = mt * 32 + mf * 16 + (lid & 15);
        const int c = kc * 2 + (lid >> 4);
        return sb + base + r * 128 + ((c ^ sw8(r)) << 4);
    };
    auto wAddr = [&](int jj, int half) -> uint32_t {
        const int n = nq * 64 + jj * 16 + (lid & 15);
        const int c = half * 2 + (lid >> 4);
        return sb + W1T + n * 64 + ((c ^ (n & 3)) << 4);
    };
    // 3-term bf16 chunk (2 m-frags)
    auto rec3 = [&](float (*acc)[8][4], int aHi, int aLo, int bHi, int bLo, int kc) {
        uint32_t ah[2][4], al[2][4], bh[16], bl[16];
        ldsm4(aAddr(aHi, 0, kc), ah[0]); ldsm4(aAddr(aHi, 1, kc), ah[1]);
        ldsm4(aAddr(aLo, 0, kc), al[0]); ldsm4(aAddr(aLo, 1, kc), al[1]);
#pragma unroll
        for (int jj = 0; jj < 4; ++jj) {
            ldsm4(bAddr(bHi, jj, kc), bh + 4 * jj);
            ldsm4(bAddr(bLo, jj, kc), bl + 4 * jj);
        }
#pragma unroll
        for (int m = 0; m < 2; ++m)
#pragma unroll
            for (int jj = 0; jj < 4; ++jj) {
                mmab(acc[m][2 * jj], ah[m], bh[4 * jj], bh[4 * jj + 2]);
                mmab(acc[m][2 * jj + 1], ah[m], bh[4 * jj + 1], bh[4 * jj + 3]);
                mmab(acc[m][2 * jj], al[m], bh[4 * jj], bh[4 * jj + 2]);
                mmab(acc[m][2 * jj + 1], al[m], bh[4 * jj + 1], bh[4 * jj + 3]);
                mmab(acc[m][2 * jj], ah[m], bl[4 * jj], bl[4 * jj + 2]);
                mmab(acc[m][2 * jj + 1], ah[m], bl[4 * jj + 1], bl[4 * jj + 3]);
            }
    };
    // 2-term fp16 chunk (h2 @ U2)
    auto rec2 = [&](float (*acc)[8][4], int aHi, int aLo, int bB, int kc) {
        uint32_t ah[2][4], al[2][4], bh[16];
        ldsm4(aAddr(aHi, 0, kc), ah[0]); ldsm4(aAddr(aHi, 1, kc), ah[1]);
        ldsm4(aAddr(aLo, 0, kc), al[0]); ldsm4(aAddr(aLo, 1, kc), al[1]);
#pragma unroll
        for (int jj = 0; jj < 4; ++jj) ldsm4(bAddr(bB, jj, kc), bh + 4 * jj);
#pragma unroll
        for (int m = 0; m < 2; ++m)
#pragma unroll
            for (int jj = 0; jj < 4; ++jj) {
                mmah(acc[m][2 * jj], ah[m], bh[4 * jj], bh[4 * jj + 2]);
                mmah(acc[m][2 * jj + 1], ah[m], bh[4 * jj + 1], bh[4 * jj + 3]);
                mmah(acc[m][2 * jj], al[m], bh[4 * jj], bh[4 * jj + 2]);
                mmah(acc[m][2 * jj + 1], al[m], bh[4 * jj + 1], bh[4 * jj + 3]);
            }
    };
    // epilogue (both m-frags): gates in-register -> h tiles (bf16 or fp16)
    auto epi = [&](float (*acc)[8][4], float (*cst)[8], const float* bs,
                   int hHi, int hLo, bool relu, bool fp16h, bool head, float (*pout)[2][4]) {
#pragma unroll
        for (int m = 0; m < 2; ++m)
#pragma unroll
            for (int j2 = 0; j2 < 2; ++j2)
#pragma unroll
                for (int r = 0; r < 4; ++r) {
                    const int u = nq * 16 + j2 * 8 + tig * 2 + (r & 1);
                    const int s = mt * 32 + m * 16 + grp + (r >> 1) * 8;
                    const float iv = sigm(acc[m][j2][r] + bs[u]);
                    const float fv = sigm(acc[m][2 + j2][r] + bs[64 + u]);
                    const float zg = acc[m][4 + j2][r] + bs[128 + u];
                    const float gv = relu ? fmaxf(zg, 0.f) : tha(zg);
                    const float ov = sigm(acc[m][6 + j2][r] + bs[192 + u]);
                    const int ci = j2 * 4 + r;
                    const float cc = fmaf(fv, cst[m][ci], iv * gv);
                    cst[m][ci] = cc;
                    const float hv = ov * (relu ? fmaxf(cc, 0.f) : tha(cc));
                    const int ad = s * 128 + (((u >> 3) ^ sw8(s)) << 4) + (u & 7) * 2;
                    if (fp16h) {
                        *reinterpret_cast<__half*>(sm + hHi + ad) = __float2half(hv);
                        *reinterpret_cast<__half*>(sm + hLo + ad) = __float2half(hv - hfr(hv));
                    } else {
                        *reinterpret_cast<__nv_bfloat16*>(sm + hHi + ad) = __float2bfloat16(hv);
                        *reinterpret_cast<__nv_bfloat16*>(sm + hLo + ad) = __float2bfloat16(hv - bfr(hv));
                    }
                    if (head) {
                        const float4 w = *reinterpret_cast<const float4*>(Wf + u * 4);
                        float* po = pout[m][r >> 1];
                        po[0] = fmaf(hv, w.x, po[0]);
                        po[1] = fmaf(hv, w.y, po[1]);
                        po[2] = fmaf(hv, w.z, po[2]);
                        po[3] = fmaf(hv, w.w, po[3]);
                    }
                }
    };

    // ---- persistent tile loop: 64 samples/tile ----
    for (int tile = blockIdx.x; tile < NTILES; tile += gridDim.x) {
        float c1[2][8], c2[2][8], pout[2][2][4];
#pragma unroll
        for (int m = 0; m < 2; ++m)
#pragma unroll
            for (int i = 0; i < 8; ++i) { c1[m][i] = 0.f; c2[m][i] = 0.f; }
#pragma unroll
        for (int m = 0; m < 2; ++m)
#pragma unroll
            for (int h = 0; h < 2; ++h)
#pragma unroll
                for (int i = 0; i < 4; ++i) pout[m][h][i] = 0.f;
        const float* xb = x + (size_t)(tile * 64 + mt * 32 + grp) * (TT * 16) + tig * 2;

        for (int t = 0; t < TT; ++t) {
            uint32_t axh[2][4], axl[2][4];
#pragma unroll
            for (int m = 0; m < 2; ++m) {
                const float* px = xb + (size_t)m * 16 * (TT * 16) + t * 16;
                const float2 v0 = *reinterpret_cast<const float2*>(px);
                const float2 v1 = *reinterpret_cast<const float2*>(px + 8 * TT * 16);
                const float2 v2 = *reinterpret_cast<const float2*>(px + 8);
                const float2 v3 = *reinterpret_cast<const float2*>(px + 8 * TT * 16 + 8);
                axh[m][0] = pk(v0.x, v0.y); axh[m][1] = pk(v1.x, v1.y);
                axh[m][2] = pk(v2.x, v2.y); axh[m][3] = pk(v3.x, v3.y);
                axl[m][0] = pk(v0.x - bfr(v0.x), v0.y - bfr(v0.y));
                axl[m][1] = pk(v1.x - bfr(v1.x), v1.y - bfr(v1.y));
                axl[m][2] = pk(v2.x - bfr(v2.x), v2.y - bfr(v2.y));
                axl[m][3] = pk(v3.x - bfr(v3.x), v3.y - bfr(v3.y));
            }

            // ---- z1 = x@W1 + h1@U1 ----
            float acc[2][8][4];
#pragma unroll
            for (int m = 0; m < 2; ++m)
#pragma unroll
                for (int j = 0; j < 8; ++j)
#pragma unroll
                    for (int r = 0; r < 4; ++r) acc[m][j][r] = 0.f;
            {
                uint32_t bh[16], bl[16];
#pragma unroll
                for (int jj = 0; jj < 4; ++jj) {
                    ldsm4(wAddr(jj, 0), bh + 4 * jj);
                    ldsm4(wAddr(jj, 1), bl + 4 * jj);
                }
#pragma unroll
                for (int m = 0; m < 2; ++m)
#pragma unroll
                    for (int jj = 0; jj < 4; ++jj) {
                        mmab(acc[m][2 * jj], axh[m], bh[4 * jj], bh[4 * jj + 2]);
                        mmab(acc[m][2 * jj + 1], axh[m], bh[4 * jj + 1], bh[4 * jj + 3]);
                        mmab(acc[m][2 * jj], axl[m], bh[4 * jj], bh[4 * jj + 2]);
                        mmab(acc[m][2 * jj + 1], axl[m], bh[4 * jj + 1], bh[4 * jj + 3]);
                        mmab(acc[m][2 * jj], axh[m], bl[4 * jj], bl[4 * jj + 2]);
                        mmab(acc[m][2 * jj + 1], axh[m], bl[4 * jj + 1], bl[4 * jj + 3]);
                    }
            }
            if (t)
#pragma unroll
                for (int kc = 0; kc < 4; ++kc) rec3(acc, HT1HI, HT1LO, U1HI, U1LO, kc);
            __syncthreads();
            epi(acc, c1, b1s, HT1HI, HT1LO, false, false, false, nullptr);
            __syncthreads();

            // ---- z2 = h1@Wfused + h2@U2(fp16) ----
            float acc2[2][8][4];
#pragma unroll
            for (int m = 0; m < 2; ++m)
#pragma unroll
                for (int j = 0; j < 8; ++j)
#pragma unroll
                    for (int r = 0; r < 4; ++r) acc2[m][j][r] = 0.f;
#pragma unroll
            for (int kc = 0; kc < 4; ++kc) rec3(acc2, HT1HI, HT1LO, FHI, FLO, kc);
            if (t)
#pragma unroll
                for (int kc = 0; kc < 4; ++kc) rec2(acc2, HT2HI, HT2LO, U2F, kc);
            __syncthreads();
            epi(acc2, c2, b2s, HT2HI, HT2LO, true, true, t == TT - 1, pout);
            __syncthreads();
        }

        // ---- head: shfl-reduce over tig, smem-reduce over nq ----
#pragma unroll
        for (int m = 0; m < 2; ++m)
#pragma unroll
            for (int h = 0; h < 2; ++h)
#pragma unroll
                for (int o = 0; o < 4; ++o) {
                    pout[m][h][o] += __shfl_xor_sync(0xffffffffu, pout[m][h][o], 1);
                    pout[m][h][o] += __shfl_xor_sync(0xffffffffu, pout[m][h][o], 2);
                }
        float* scr = reinterpret_cast<float*>(sm + HT1HI);   // h1hi dead after last z2
        __syncthreads();
        if (tig == 0)
#pragma unroll
            for (int m = 0; m < 2; ++m)
#pragma unroll
                for (int h = 0; h < 2; ++h) {
                    const int s0 = mt * 32 + m * 16 + grp + h * 8;
                    *reinterpret_cast<float4*>(scr + (s0 * 4 + nq) * 4) =
                        make_float4(pout[m][h][0], pout[m][h][1], pout[m][h][2], pout[m][h][3]);
                }
        __syncthreads();
        {
            const int s = tid >> 2, o = tid & 3;   // 64 samples x 4 outs = 256 threads
            const float v = scr[(s * 4 + 0) * 4 + o] + scr[(s * 4 + 1) * 4 + o] +
                            scr[(s * 4 + 2) * 4 + o] + scr[(s * 4 + 3) * 4 + o] + bf[o];
            out[(size_t)tile * 256 + s * 4 + o] = v;
        }
        __syncthreads();
    }
}

extern "C" void kernel_launch(void* const* d_in, const int* in_sizes, int n_in,
                              void* d_out, int out_size) {
    (void)in_sizes; (void)n_in; (void)out_size;
    const float* x  = (const float*)d_in[0];
    const float* W1 = (const float*)d_in[1];
    const float* U1 = (const float*)d_in[2];
    const float* b1 = (const float*)d_in[3];
    const float* Wd = (const float*)d_in[4];
    const float* bd = (const float*)d_in[5];
    const float* W2 = (const float*)d_in[6];
    const float* U2 = (const float*)d_in[7];
    const float* b2 = (const float*)d_in[8];
    const float* Wf = (const float*)d_in[9];
    const float* bf = (const float*)d_in[10];
    float* out = (float*)d_out;

    prep_kernel<<<1, 256>>>(Wd, bd, W2, b2);
    cudaFuncSetAttribute(rnn_mma_kernel, cudaFuncAttributeMaxDynamicSharedMemorySize, SMEM_BYTES);
    rnn_mma_kernel<<<GRID, 256, SMEM_BYTES>>>(x, W1, U1, b1, U2, Wf, bf, out);
}

// round 9
// speedup vs baseline: 3.0059x; 1.4016x over previous
#include <cuda_runtime.h>
#include <cuda_bf16.h>
#include <cuda_fp16.h>
#include <cstdint>

namespace {
constexpr int TT = 10;
constexpr int NTILES = 1024;      // 65536 / 64 samples per tile
constexpr int GRID = 148;
// fp16 B-tiles [256 n][64 k], 128B rows, swizzled
constexpr int U1F = 0, FF = 32768, U2F = 65536;
constexpr int W1T = 98304;        // bf16 [256 n][32 k]: k0-15 hi, k16-31 lo (64B rows)
constexpr int HT1 = 114688;       // h1 bufs: base + buf*16384 (hi), +8192 (lo), fp16 [64s][64u]
constexpr int HT2 = 147456;       // h2 bufs, same layout
constexpr int BIAS1 = 180224, BIAS2 = 181248;
constexpr int SMEM_BYTES = 182272;
}

__device__ float g_Wf[64 * 256];
__device__ float g_b2p[256];

__device__ __forceinline__ uint32_t s2u(const void* p) {
    uint32_t a;
    asm("{.reg .u64 t; cvta.to.shared.u64 t,%1; cvt.u32.u64 %0,t;}" : "=r"(a) : "l"(p));
    return a;
}
__device__ __forceinline__ void ldsm4(uint32_t a, uint32_t* r) {
    asm volatile("ldmatrix.sync.aligned.m8n8.x4.shared.b16 {%0,%1,%2,%3},[%4];"
        : "=r"(r[0]), "=r"(r[1]), "=r"(r[2]), "=r"(r[3]) : "r"(a));
}
__device__ __forceinline__ void mmab(float* d, const uint32_t* a, uint32_t b0, uint32_t b1) {
    asm volatile("mma.sync.aligned.m16n8k16.row.col.f32.bf16.bf16.f32 "
        "{%0,%1,%2,%3},{%4,%5,%6,%7},{%8,%9},{%0,%1,%2,%3};"
        : "+f"(d[0]), "+f"(d[1]), "+f"(d[2]), "+f"(d[3])
        : "r"(a[0]), "r"(a[1]), "r"(a[2]), "r"(a[3]), "r"(b0), "r"(b1));
}
__device__ __forceinline__ void mmah(float* d, const uint32_t* a, uint32_t b0, uint32_t b1) {
    asm volatile("mma.sync.aligned.m16n8k16.row.col.f32.f16.f16.f32 "
        "{%0,%1,%2,%3},{%4,%5,%6,%7},{%8,%9},{%0,%1,%2,%3};"
        : "+f"(d[0]), "+f"(d[1]), "+f"(d[2]), "+f"(d[3])
        : "r"(a[0]), "r"(a[1]), "r"(a[2]), "r"(a[3]), "r"(b0), "r"(b1));
}
__device__ __forceinline__ float tapx(float x) {
    float r;
    asm("tanh.approx.f32 %0,%1;" : "=f"(r) : "f"(x));
    return r;
}
__device__ __forceinline__ float sigm(float x) { return fmaf(tapx(0.5f * x), 0.5f, 0.5f); }
__device__ __forceinline__ uint32_t pk(float a, float b) {
    __nv_bfloat162 t = __floats2bfloat162_rn(a, b);
    return *reinterpret_cast<uint32_t*>(&t);
}
__device__ __forceinline__ uint32_t pkh(float a, float b) {
    __half2 t = __floats2half2_rn(a, b);
    return *reinterpret_cast<uint32_t*>(&t);
}
__device__ __forceinline__ float bfr(float v) { return __bfloat162float(__float2bfloat16(v)); }
__device__ __forceinline__ float hfr(float v) { return __half2float(__float2half(v)); }
__device__ __forceinline__ int sw8(int r) { return (r + (r >> 3)) & 7; }

__global__ void prep_kernel(const float* __restrict__ Wd, const float* __restrict__ bd,
                            const float* __restrict__ W2, const float* __restrict__ b2) {
    const int n = threadIdx.x;
    float s2 = b2[n];
    for (int j = 0; j < 30; ++j) s2 += bd[j] * W2[j * 256 + n];
    g_b2p[n] = s2;
    for (int k = 0; k < 64; ++k) {
        float s = 0.f;
        for (int j = 0; j < 30; ++j) s += Wd[k * 30 + j] * W2[j * 256 + n];
        g_Wf[k * 256 + n] = s;
    }
}

__global__ void __launch_bounds__(256, 1)
rnn_mma_kernel(const float* __restrict__ x, const float* __restrict__ W1,
               const float* __restrict__ U1, const float* __restrict__ b1,
               const float* __restrict__ U2, const float* __restrict__ Wf,
               const float* __restrict__ bf, float* __restrict__ out)
{
    extern __shared__ char sm[];
    const uint32_t sb = s2u(sm);
    const int tid = threadIdx.x, wid = tid >> 5, lid = tid & 31;
    const int mt = wid & 1, nq = wid >> 1;
    const int grp = lid >> 2, tig = lid & 3;
    float* b1s = reinterpret_cast<float*>(sm + BIAS1);
    float* b2s = reinterpret_cast<float*>(sm + BIAS2);

    auto ocol = [](int p) { return (((p >> 4) & 3) << 6) + ((p >> 6) << 4) + (p & 15); };

    // ---- stage weights once (fp16 single for U1/F/U2, bf16 hi/lo for W1) ----
    auto stageH = [&](const float* src, int off) {
        for (int idx = tid; idx < 2048; idx += 256) {
            const int p = idx >> 3, kc = idx & 7;
            const float* s0 = src + ocol(p);
            uint32_t v[4];
#pragma unroll
            for (int i = 0; i < 4; ++i)
                v[i] = pkh(s0[(kc * 8 + 2 * i) * 256], s0[(kc * 8 + 2 * i + 1) * 256]);
            *reinterpret_cast<uint4*>(sm + off + p * 128 + ((kc ^ sw8(p)) << 4)) =
                *reinterpret_cast<uint4*>(v);
        }
    };
    stageH(U1, U1F);
    stageH(g_Wf, FF);
    stageH(U2, U2F);
    for (int idx = tid; idx < 1024; idx += 256) {   // W1 bf16 hi/lo
        const int p = idx >> 2, c = idx & 3, oc = ocol(p);
        const bool isLo = c >= 2;
        const int kb = (c & 1) * 8;
        uint32_t v[4];
#pragma unroll
        for (int i = 0; i < 4; ++i) {
            float a = W1[(kb + 2 * i) * 256 + oc];
            float b = W1[(kb + 2 * i + 1) * 256 + oc];
            if (isLo) { a -= bfr(a); b -= bfr(b); }
            v[i] = pk(a, b);
        }
        *reinterpret_cast<uint4*>(sm + W1T + p * 64 + ((c ^ (p & 3)) << 4)) =
            *reinterpret_cast<uint4*>(v);
    }
    b1s[tid] = b1[tid];
    b2s[tid] = g_b2p[tid];
    __syncthreads();

    auto bAddr = [&](int base, int jj, int kc) -> uint32_t {
        const int n = nq * 64 + jj * 16 + (lid & 15);
        const int c = kc * 2 + (lid >> 4);
        return sb + base + n * 128 + ((c ^ sw8(n)) << 4);
    };
    auto aAddr = [&](int base, int mf, int kc) -> uint32_t {
        const int r = mt * 32 + mf * 16 + (lid & 15);
        const int c = kc * 2 + (lid >> 4);
        return sb + base + r * 128 + ((c ^ sw8(r)) << 4);
    };
    auto wAddr = [&](int jj, int half) -> uint32_t {
        const int n = nq * 64 + jj * 16 + (lid & 15);
        const int c = half * 2 + (lid >> 4);
        return sb + W1T + n * 64 + ((c ^ (n & 3)) << 4);
    };
    // fp16 2-term chunk: acc += Ahi*B + Alo*B   (A = h split hi/lo fp16, B single fp16)
    auto rec2 = [&](float (*acc)[8][4], int aBase, int bBase, int kc) {
        uint32_t ah[2][4], al[2][4], bh[16];
        ldsm4(aAddr(aBase, 0, kc), ah[0]); ldsm4(aAddr(aBase, 1, kc), ah[1]);
        ldsm4(aAddr(aBase + 8192, 0, kc), al[0]); ldsm4(aAddr(aBase + 8192, 1, kc), al[1]);
#pragma unroll
        for (int jj = 0; jj < 4; ++jj) ldsm4(bAddr(bBase, jj, kc), bh + 4 * jj);
#pragma unroll
        for (int m = 0; m < 2; ++m)
#pragma unroll
            for (int jj = 0; jj < 4; ++jj) {
                mmah(acc[m][2 * jj], ah[m], bh[4 * jj], bh[4 * jj + 2]);
                mmah(acc[m][2 * jj + 1], ah[m], bh[4 * jj + 1], bh[4 * jj + 3]);
                mmah(acc[m][2 * jj], al[m], bh[4 * jj], bh[4 * jj + 2]);
                mmah(acc[m][2 * jj + 1], al[m], bh[4 * jj + 1], bh[4 * jj + 3]);
            }
    };
    // epilogue: gates in-register -> LSTM -> fp16 hi/lo h tile at hBase
    auto epi = [&](float (*acc)[8][4], float (*cst)[8], const float* bs,
                   int hBase, bool relu, bool head, float (*pout)[2][4]) {
#pragma unroll
        for (int m = 0; m < 2; ++m)
#pragma unroll
            for (int j2 = 0; j2 < 2; ++j2)
#pragma unroll
                for (int r = 0; r < 4; ++r) {
                    const int u = nq * 16 + j2 * 8 + tig * 2 + (r & 1);
                    const int s = mt * 32 + m * 16 + grp + (r >> 1) * 8;
                    const float iv = sigm(acc[m][j2][r] + bs[u]);
                    const float fv = sigm(acc[m][2 + j2][r] + bs[64 + u]);
                    const float zg = acc[m][4 + j2][r] + bs[128 + u];
                    const float gv = relu ? fmaxf(zg, 0.f) : tapx(zg);
                    const float ov = sigm(acc[m][6 + j2][r] + bs[192 + u]);
                    const int ci = j2 * 4 + r;
                    const float cc = fmaf(fv, cst[m][ci], iv * gv);
                    cst[m][ci] = cc;
                    const float hv = ov * (relu ? fmaxf(cc, 0.f) : tapx(cc));
                    const int ad = s * 128 + (((u >> 3) ^ sw8(s)) << 4) + (u & 7) * 2;
                    *reinterpret_cast<__half*>(sm + hBase + ad) = __float2half(hv);
                    *reinterpret_cast<__half*>(sm + hBase + 8192 + ad) = __float2half(hv - hfr(hv));
                    if (head) {
                        const float4 w = *reinterpret_cast<const float4*>(Wf + u * 4);
                        float* po = pout[m][r >> 1];
                        po[0] = fmaf(hv, w.x, po[0]);
                        po[1] = fmaf(hv, w.y, po[1]);
                        po[2] = fmaf(hv, w.z, po[2]);
                        po[3] = fmaf(hv, w.w, po[3]);
                    }
                }
    };

    // ---- persistent tile loop: 64 samples/tile ----
    for (int tile = blockIdx.x; tile < NTILES; tile += gridDim.x) {
        float c1[2][8], c2[2][8], pout[2][2][4];
#pragma unroll
        for (int m = 0; m < 2; ++m)
#pragma unroll
            for (int i = 0; i < 8; ++i) { c1[m][i] = 0.f; c2[m][i] = 0.f; }
#pragma unroll
        for (int m = 0; m < 2; ++m)
#pragma unroll
            for (int h = 0; h < 2; ++h)
#pragma unroll
                for (int i = 0; i < 4; ++i) pout[m][h][i] = 0.f;
        const float* xb = x + (size_t)(tile * 64 + mt * 32 + grp) * (TT * 16) + tig * 2;

        for (int t = 0; t < TT; ++t) {
            const int cb = (t & 1) * 16384, pb = ((t & 1) ^ 1) * 16384;
            // issue x loads first (consumed after the recurrent MMA chunk)
            float2 v[2][4];
#pragma unroll
            for (int m = 0; m < 2; ++m) {
                const float* px = xb + (size_t)m * 16 * (TT * 16) + t * 16;
                v[m][0] = *reinterpret_cast<const float2*>(px);
                v[m][1] = *reinterpret_cast<const float2*>(px + 8 * TT * 16);
                v[m][2] = *reinterpret_cast<const float2*>(px + 8);
                v[m][3] = *reinterpret_cast<const float2*>(px + 8 * TT * 16 + 8);
            }

            // ---- z1 = h1@U1 (fp16) + x@W1 (bf16 3-term) ----
            float acc[2][8][4];
#pragma unroll
            for (int m = 0; m < 2; ++m)
#pragma unroll
                for (int j = 0; j < 8; ++j)
#pragma unroll
                    for (int r = 0; r < 4; ++r) acc[m][j][r] = 0.f;
            if (t)
#pragma unroll
                for (int kc = 0; kc < 4; ++kc) rec2(acc, HT1 + pb, U1F, kc);
            {
                uint32_t axh[2][4], axl[2][4];
#pragma unroll
                for (int m = 0; m < 2; ++m)
#pragma unroll
                    for (int i = 0; i < 4; ++i) {
                        axh[m][i] = pk(v[m][i].x, v[m][i].y);
                        axl[m][i] = pk(v[m][i].x - bfr(v[m][i].x), v[m][i].y - bfr(v[m][i].y));
                    }
                uint32_t bh[16], bl[16];
#pragma unroll
                for (int jj = 0; jj < 4; ++jj) {
                    ldsm4(wAddr(jj, 0), bh + 4 * jj);
                    ldsm4(wAddr(jj, 1), bl + 4 * jj);
                }
#pragma unroll
                for (int m = 0; m < 2; ++m)
#pragma unroll
                    for (int jj = 0; jj < 4; ++jj) {
                        mmab(acc[m][2 * jj], axh[m], bh[4 * jj], bh[4 * jj + 2]);
                        mmab(acc[m][2 * jj + 1], axh[m], bh[4 * jj + 1], bh[4 * jj + 3]);
                        mmab(acc[m][2 * jj], axl[m], bh[4 * jj], bh[4 * jj + 2]);
                        mmab(acc[m][2 * jj + 1], axl[m], bh[4 * jj + 1], bh[4 * jj + 3]);
                        mmab(acc[m][2 * jj], axh[m], bl[4 * jj], bl[4 * jj + 2]);
                        mmab(acc[m][2 * jj + 1], axh[m], bl[4 * jj + 1], bl[4 * jj + 3]);
                    }
            }
            // epi1 writes the ALTERNATE h1 buffer -> no barrier needed before it
            epi(acc, c1, b1s, HT1 + cb, false, false, nullptr);
            __syncthreads();   // h1[cb] visible

            // ---- z2 = h1@Wfused + h2@U2 (both fp16 2-term) ----
            float acc2[2][8][4];
#pragma unroll
            for (int m = 0; m < 2; ++m)
#pragma unroll
                for (int j = 0; j < 8; ++j)
#pragma unroll
                    for (int r = 0; r < 4; ++r) acc2[m][j][r] = 0.f;
#pragma unroll
            for (int kc = 0; kc < 4; ++kc) rec2(acc2, HT1 + cb, FF, kc);
            if (t)
#pragma unroll
                for (int kc = 0; kc < 4; ++kc) rec2(acc2, HT2 + pb, U2F, kc);
            epi(acc2, c2, b2s, HT2 + cb, true, t == TT - 1, pout);
            __syncthreads();   // h2[cb] visible
        }

        // ---- head: shfl-reduce over tig, smem-reduce over nq ----
#pragma unroll
        for (int m = 0; m < 2; ++m)
#pragma unroll
            for (int h = 0; h < 2; ++h)
#pragma unroll
                for (int o = 0; o < 4; ++o) {
                    pout[m][h][o] += __shfl_xor_sync(0xffffffffu, pout[m][h][o], 1);
                    pout[m][h][o] += __shfl_xor_sync(0xffffffffu, pout[m][h][o], 2);
                }
        float* scr = reinterpret_cast<float*>(sm + HT1);   // h1 dead after last z2
        if (tig == 0)
#pragma unroll
            for (int m = 0; m < 2; ++m)
#pragma unroll
                for (int h = 0; h < 2; ++h) {
                    const int s0 = mt * 32 + m * 16 + grp + h * 8;
                    *reinterpret_cast<float4*>(scr + (s0 * 4 + nq) * 4) =
                        make_float4(pout[m][h][0], pout[m][h][1], pout[m][h][2], pout[m][h][3]);
                }
        __syncthreads();
        {
            const int s = tid >> 2, o = tid & 3;
            const float vv = scr[(s * 4 + 0) * 4 + o] + scr[(s * 4 + 1) * 4 + o] +
                             scr[(s * 4 + 2) * 4 + o] + scr[(s * 4 + 3) * 4 + o] + bf[o];
            out[(size_t)tile * 256 + s * 4 + o] = vv;
        }
        __syncthreads();   // scr reads done before next tile's epi1 writes h1
    }
}

extern "C" void kernel_launch(void* const* d_in, const int* in_sizes, int n_in,
                              void* d_out, int out_size) {
    (void)in_sizes; (void)n_in; (void)out_size;
    const float* x  = (const float*)d_in[0];
    const float* W1 = (const float*)d_in[1];
    const float* U1 = (const float*)d_in[2];
    const float* b1 = (const float*)d_in[3];
    const float* Wd = (const float*)d_in[4];
    const float* bd = (const float*)d_in[5];
    const float* W2 = (const float*)d_in[6];
    const float* U2 = (const float*)d_in[7];
    const float* b2 = (const float*)d_in[8];
    const float* Wf = (const float*)d_in[9];
    const float* bf = (const float*)d_in[10];
    float* out = (float*)d_out;

    prep_kernel<<<1, 256>>>(Wd, bd, W2, b2);
    cudaFuncSetAttribute(rnn_mma_kernel, cudaFuncAttributeMaxDynamicSharedMemorySize, SMEM_BYTES);
    rnn_mma_kernel<<<GRID, 256, SMEM_BYTES>>>(x, W1, U1, b1, U2, Wf, bf, out);
}

// round 10
// speedup vs baseline: 3.5249x; 1.1727x over previous
#include <cuda_runtime.h>
#include <cuda_bf16.h>
#include <cuda_fp16.h>
#include <cstdint>

namespace {
constexpr int TT = 10;
constexpr int NTILES = 1024;      // 65536 / 64 samples per tile
constexpr int GRID = 148;
// fp16 B-tiles [256 n][64 k], 128B rows, swizzled
constexpr int U1F = 0, FF = 32768, U2F = 65536;
constexpr int W1T = 98304;        // fp16 [256 n][32 k] (k0-15 data), 64B rows
constexpr int HT1 = 114688;       // h1: + buf*16384 (hi), +8192 (lo); fp16 [64s][64u]
constexpr int HT2 = 147456;       // h2 same layout
constexpr int BIAS1 = 180224, BIAS2 = 181248;   // interleaved [u*4 + gate] f32
constexpr int SMEM_BYTES = 182272;
}

__device__ float g_Wf[64 * 256];
__device__ float g_b2p[256];

__device__ __forceinline__ uint32_t s2u(const void* p) {
    uint32_t a;
    asm("{.reg .u64 t; cvta.to.shared.u64 t,%1; cvt.u32.u64 %0,t;}" : "=r"(a) : "l"(p));
    return a;
}
__device__ __forceinline__ void ldsm4(uint32_t a, uint32_t* r) {
    asm volatile("ldmatrix.sync.aligned.m8n8.x4.shared.b16 {%0,%1,%2,%3},[%4];"
        : "=r"(r[0]), "=r"(r[1]), "=r"(r[2]), "=r"(r[3]) : "r"(a));
}
__device__ __forceinline__ void mmah(float* d, const uint32_t* a, uint32_t b0, uint32_t b1) {
    asm volatile("mma.sync.aligned.m16n8k16.row.col.f32.f16.f16.f32 "
        "{%0,%1,%2,%3},{%4,%5,%6,%7},{%8,%9},{%0,%1,%2,%3};"
        : "+f"(d[0]), "+f"(d[1]), "+f"(d[2]), "+f"(d[3])
        : "r"(a[0]), "r"(a[1]), "r"(a[2]), "r"(a[3]), "r"(b0), "r"(b1));
}
__device__ __forceinline__ float tapx(float x) {
    float r;
    asm("tanh.approx.f32 %0,%1;" : "=f"(r) : "f"(x));
    return r;
}
__device__ __forceinline__ float sigm(float x) { return fmaf(tapx(0.5f * x), 0.5f, 0.5f); }
__device__ __forceinline__ uint32_t pkh(float a, float b) {
    __half2 t = __floats2half2_rn(a, b);
    return *reinterpret_cast<uint32_t*>(&t);
}
__device__ __forceinline__ float hfr(float v) { return __half2float(__float2half(v)); }
__device__ __forceinline__ int sw8(int r) { return (r + (r >> 3)) & 7; }

__global__ void prep_kernel(const float* __restrict__ Wd, const float* __restrict__ bd,
                            const float* __restrict__ W2, const float* __restrict__ b2) {
    const int n = threadIdx.x;
    float s2 = b2[n];
    for (int j = 0; j < 30; ++j) s2 += bd[j] * W2[j * 256 + n];
    g_b2p[n] = s2;
    for (int k = 0; k < 64; ++k) {
        float s = 0.f;
        for (int j = 0; j < 30; ++j) s += Wd[k * 30 + j] * W2[j * 256 + n];
        g_Wf[k * 256 + n] = s;
    }
}

__global__ void __launch_bounds__(256, 1)
rnn_mma_kernel(const float* __restrict__ x, const float* __restrict__ W1,
               const float* __restrict__ U1, const float* __restrict__ b1,
               const float* __restrict__ U2, const float* __restrict__ Wf,
               const float* __restrict__ bf, float* __restrict__ out)
{
    extern __shared__ char sm[];
    const uint32_t sb = s2u(sm);
    const int tid = threadIdx.x, wid = tid >> 5, lid = tid & 31;
    const int mt = wid & 1, nq = wid >> 1;
    const int grp = lid >> 2, tig = lid & 3;

    auto ocol = [](int p) { return (((p >> 4) & 3) << 6) + ((p >> 6) << 4) + (p & 15); };

    // ---- stage weights once (fp16 single) ----
    auto stageH = [&](const float* src, int off) {
        for (int idx = tid; idx < 2048; idx += 256) {
            const int p = idx >> 3, kc = idx & 7;
            const float* s0 = src + ocol(p);
            uint32_t v[4];
#pragma unroll
            for (int i = 0; i < 4; ++i)
                v[i] = pkh(s0[(kc * 8 + 2 * i) * 256], s0[(kc * 8 + 2 * i + 1) * 256]);
            *reinterpret_cast<uint4*>(sm + off + p * 128 + ((kc ^ sw8(p)) << 4)) =
                *reinterpret_cast<uint4*>(v);
        }
    };
    stageH(U1, U1F);
    stageH(g_Wf, FF);
    stageH(U2, U2F);
    for (int idx = tid; idx < 512; idx += 256) {    // W1 fp16 [256][32k], data in k0-15
        const int p = idx >> 1, c = idx & 1, oc = ocol(p);
        uint32_t v[4];
#pragma unroll
        for (int i = 0; i < 4; ++i)
            v[i] = pkh(W1[(c * 8 + 2 * i) * 256 + oc], W1[(c * 8 + 2 * i + 1) * 256 + oc]);
        *reinterpret_cast<uint4*>(sm + W1T + p * 64 + ((c ^ (p & 3)) << 4)) =
            *reinterpret_cast<uint4*>(v);
    }
    {   // biases interleaved: bi[u*4+g] = b[g*64+u]
        float* b1i = reinterpret_cast<float*>(sm + BIAS1);
        float* b2i = reinterpret_cast<float*>(sm + BIAS2);
        const int u = tid >> 2, g = tid & 3;
        b1i[tid] = b1[g * 64 + u];
        b2i[tid] = g_b2p[g * 64 + u];
    }
    __syncthreads();

    // bias registers: bv[layer][j2*2+e][gate]
    float b1v[4][4], b2v[4][4];
#pragma unroll
    for (int j2 = 0; j2 < 2; ++j2)
#pragma unroll
        for (int e = 0; e < 2; ++e) {
            const int u = nq * 16 + j2 * 8 + tig * 2 + e;
            *reinterpret_cast<float4*>(b1v[j2 * 2 + e]) =
                *reinterpret_cast<const float4*>(reinterpret_cast<float*>(sm + BIAS1) + u * 4);
            *reinterpret_cast<float4*>(b2v[j2 * 2 + e]) =
                *reinterpret_cast<const float4*>(reinterpret_cast<float*>(sm + BIAS2) + u * 4);
        }

    auto bAddr = [&](int base, int jj, int kc) -> uint32_t {
        const int n = nq * 64 + jj * 16 + (lid & 15);
        const int c = kc * 2 + (lid >> 4);
        return sb + base + n * 128 + ((c ^ sw8(n)) << 4);
    };
    auto aAddr = [&](int base, int mf, int kc) -> uint32_t {
        const int r = mt * 32 + mf * 16 + (lid & 15);
        const int c = kc * 2 + (lid >> 4);
        return sb + base + r * 128 + ((c ^ sw8(r)) << 4);
    };
    auto wAddr = [&](int jj) -> uint32_t {
        const int n = nq * 64 + jj * 16 + (lid & 15);
        const int c = lid >> 4;
        return sb + W1T + n * 64 + ((c ^ (n & 3)) << 4);
    };
    // fp16 2-term chunk: acc += Ahi*B + Alo*B
    auto rec2 = [&](float (*acc)[8][4], int aBase, int bBase, int kc) {
        uint32_t ah[2][4], al[2][4], bh[16];
        ldsm4(aAddr(aBase, 0, kc), ah[0]); ldsm4(aAddr(aBase, 1, kc), ah[1]);
        ldsm4(aAddr(aBase + 8192, 0, kc), al[0]); ldsm4(aAddr(aBase + 8192, 1, kc), al[1]);
#pragma unroll
        for (int jj = 0; jj < 4; ++jj) ldsm4(bAddr(bBase, jj, kc), bh + 4 * jj);
#pragma unroll
        for (int m = 0; m < 2; ++m)
#pragma unroll
            for (int jj = 0; jj < 4; ++jj) {
                mmah(acc[m][2 * jj], ah[m], bh[4 * jj], bh[4 * jj + 2]);
                mmah(acc[m][2 * jj + 1], ah[m], bh[4 * jj + 1], bh[4 * jj + 3]);
                mmah(acc[m][2 * jj], al[m], bh[4 * jj], bh[4 * jj + 2]);
                mmah(acc[m][2 * jj + 1], al[m], bh[4 * jj + 1], bh[4 * jj + 3]);
            }
    };
    // init acc from bias regs: acc[m][g*2+j2][r] = bv[j2*2 + (r&1)][g]
    auto initAcc = [&](float (*acc)[8][4], const float (*bv)[4]) {
#pragma unroll
        for (int m = 0; m < 2; ++m)
#pragma unroll
            for (int j = 0; j < 8; ++j)
#pragma unroll
                for (int r = 0; r < 4; ++r)
                    acc[m][j][r] = bv[(j & 1) * 2 + (r & 1)][j >> 1];
    };
    // epilogue: LSTM gates (bias pre-added) -> packed fp16 hi/lo stores
    auto epi = [&](float (*acc)[8][4], float (*cst)[8], int hBase,
                   bool relu, bool head, float (*pout)[2][4]) {
#pragma unroll
        for (int m = 0; m < 2; ++m)
#pragma unroll
            for (int j2 = 0; j2 < 2; ++j2)
#pragma unroll
                for (int p = 0; p < 2; ++p) {
                    float hv[2];
#pragma unroll
                    for (int e = 0; e < 2; ++e) {
                        const int r = 2 * p + e;
                        const float iv = sigm(acc[m][j2][r]);
                        const float fv = sigm(acc[m][2 + j2][r]);
                        const float gv = relu ? fmaxf(acc[m][4 + j2][r], 0.f)
                                              : tapx(acc[m][4 + j2][r]);
                        const float ov = sigm(acc[m][6 + j2][r]);
                        const int ci = j2 * 4 + r;
                        const float cc = fmaf(fv, cst[m][ci], iv * gv);
                        cst[m][ci] = cc;
                        hv[e] = ov * (relu ? fmaxf(cc, 0.f) : tapx(cc));
                        if (head) {
                            const int u = nq * 16 + j2 * 8 + tig * 2 + e;
                            const float4 w = *reinterpret_cast<const float4*>(Wf + u * 4);
                            float* po = pout[m][p];
                            po[0] = fmaf(hv[e], w.x, po[0]);
                            po[1] = fmaf(hv[e], w.y, po[1]);
                            po[2] = fmaf(hv[e], w.z, po[2]);
                            po[3] = fmaf(hv[e], w.w, po[3]);
                        }
                    }
                    const int u0 = nq * 16 + j2 * 8 + tig * 2;
                    const int s = mt * 32 + m * 16 + grp + p * 8;
                    const int ad = s * 128 + (((u0 >> 3) ^ sw8(s)) << 4) + (u0 & 7) * 2;
                    const uint32_t hi2 = pkh(hv[0], hv[1]);
                    *reinterpret_cast<uint32_t*>(sm + hBase + ad) = hi2;
                    const __half2 hh = *reinterpret_cast<const __half2*>(&hi2);
                    const float2 hf = __half22float2(hh);
                    *reinterpret_cast<uint32_t*>(sm + hBase + 8192 + ad) =
                        pkh(hv[0] - hf.x, hv[1] - hf.y);
                }
    };

    // ---- persistent tile loop: 64 samples/tile ----
    for (int tile = blockIdx.x; tile < NTILES; tile += gridDim.x) {
        float c1[2][8], c2[2][8], pout[2][2][4];
#pragma unroll
        for (int m = 0; m < 2; ++m)
#pragma unroll
            for (int i = 0; i < 8; ++i) { c1[m][i] = 0.f; c2[m][i] = 0.f; }
#pragma unroll
        for (int m = 0; m < 2; ++m)
#pragma unroll
            for (int h = 0; h < 2; ++h)
#pragma unroll
                for (int i = 0; i < 4; ++i) pout[m][h][i] = 0.f;
        const float* xb = x + (size_t)(tile * 64 + mt * 32 + grp) * (TT * 16) + tig * 2;

        for (int t = 0; t < TT; ++t) {
            const int cb = (t & 1) * 16384, pb = ((t & 1) ^ 1) * 16384;
            float2 v[2][4];
#pragma unroll
            for (int m = 0; m < 2; ++m) {
                const float* px = xb + (size_t)m * 16 * (TT * 16) + t * 16;
                v[m][0] = *reinterpret_cast<const float2*>(px);
                v[m][1] = *reinterpret_cast<const float2*>(px + 8 * TT * 16);
                v[m][2] = *reinterpret_cast<const float2*>(px + 8);
                v[m][3] = *reinterpret_cast<const float2*>(px + 8 * TT * 16 + 8);
            }

            // ---- z1 = b1 + h1@U1 + x@W1 (all fp16 2-term) ----
            float acc[2][8][4];
            initAcc(acc, b1v);
            if (t)
#pragma unroll
                for (int kc = 0; kc < 4; ++kc) rec2(acc, HT1 + pb, U1F, kc);
            {
                uint32_t axh[2][4], axl[2][4];
#pragma unroll
                for (int m = 0; m < 2; ++m)
#pragma unroll
                    for (int i = 0; i < 4; ++i) {
                        axh[m][i] = pkh(v[m][i].x, v[m][i].y);
                        axl[m][i] = pkh(v[m][i].x - hfr(v[m][i].x), v[m][i].y - hfr(v[m][i].y));
                    }
                uint32_t bh[16];
#pragma unroll
                for (int jj = 0; jj < 4; ++jj) ldsm4(wAddr(jj), bh + 4 * jj);
#pragma unroll
                for (int m = 0; m < 2; ++m)
#pragma unroll
                    for (int jj = 0; jj < 4; ++jj) {
                        mmah(acc[m][2 * jj], axh[m], bh[4 * jj], bh[4 * jj + 2]);
                        mmah(acc[m][2 * jj + 1], axh[m], bh[4 * jj + 1], bh[4 * jj + 3]);
                        mmah(acc[m][2 * jj], axl[m], bh[4 * jj], bh[4 * jj + 2]);
                        mmah(acc[m][2 * jj + 1], axl[m], bh[4 * jj + 1], bh[4 * jj + 3]);
                    }
            }
            epi(acc, c1, HT1 + cb, false, false, nullptr);
            __syncthreads();   // the ONLY barrier per timestep

            // ---- z2 = b2' + h1@Wfused + h2@U2 ----
            float acc2[2][8][4];
            initAcc(acc2, b2v);
#pragma unroll
            for (int kc = 0; kc < 4; ++kc) rec2(acc2, HT1 + cb, FF, kc);
            if (t)
#pragma unroll
                for (int kc = 0; kc < 4; ++kc) rec2(acc2, HT2 + pb, U2F, kc);
            epi(acc2, c2, HT2 + cb, true, t == TT - 1, pout);
            // no barrier: next z1 doesn't read h2; bar1(t+1) orders epi2 before z2(t+1)
        }

        // ---- head: shfl-reduce over tig, smem-reduce over nq ----
#pragma unroll
        for (int m = 0; m < 2; ++m)
#pragma unroll
            for (int h = 0; h < 2; ++h)
#pragma unroll
                for (int o = 0; o < 4; ++o) {
                    pout[m][h][o] += __shfl_xor_sync(0xffffffffu, pout[m][h][o], 1);
                    pout[m][h][o] += __shfl_xor_sync(0xffffffffu, pout[m][h][o], 2);
                }
        float* scr = reinterpret_cast<float*>(sm + HT1);   // h1 buf0 dead (last cb = buf1)
        if (tig == 0)
#pragma unroll
            for (int m = 0; m < 2; ++m)
#pragma unroll
                for (int h = 0; h < 2; ++h) {
                    const int s0 = mt * 32 + m * 16 + grp + h * 8;
                    *reinterpret_cast<float4*>(scr + (s0 * 4 + nq) * 4) =
                        make_float4(pout[m][h][0], pout[m][h][1], pout[m][h][2], pout[m][h][3]);
                }
        __syncthreads();
        {
            const int s = tid >> 2, o = tid & 3;
            const float vv = scr[(s * 4 + 0) * 4 + o] + scr[(s * 4 + 1) * 4 + o] +
                             scr[(s * 4 + 2) * 4 + o] + scr[(s * 4 + 3) * 4 + o] + bf[o];
            out[(size_t)tile * 256 + s * 4 + o] = vv;
        }
        __syncthreads();   // scr reads done before next tile's epi1 writes h1
    }
}

extern "C" void kernel_launch(void* const* d_in, const int* in_sizes, int n_in,
                              void* d_out, int out_size) {
    (void)in_sizes; (void)n_in; (void)out_size;
    const float* x  = (const float*)d_in[0];
    const float* W1 = (const float*)d_in[1];
    const float* U1 = (const float*)d_in[2];
    const float* b1 = (const float*)d_in[3];
    const float* Wd = (const float*)d_in[4];
    const float* bd = (const float*)d_in[5];
    const float* W2 = (const float*)d_in[6];
    const float* U2 = (const float*)d_in[7];
    const float* b2 = (const float*)d_in[8];
    const float* Wf = (const float*)d_in[9];
    const float* bf = (const float*)d_in[10];
    float* out = (float*)d_out;

    prep_kernel<<<1, 256>>>(Wd, bd, W2, b2);
    cudaFuncSetAttribute(rnn_mma_kernel, cudaFuncAttributeMaxDynamicSharedMemorySize, SMEM_BYTES);
    rnn_mma_kernel<<<GRID, 256, SMEM_BYTES>>>(x, W1, U1, b1, U2, Wf, bf, out);
}